// round 14
// baseline (speedup 1.0000x reference)
#include <cuda_runtime.h>
#include <cuda.h>
#include <cuda_bf16.h>
#include <cuda_fp16.h>
#include <math.h>
#include <stdint.h>

// ---------------- problem constants ----------------
#define SEGN   32
#define LSEG   512
#define RQ     64
#define POOLN  8
#define NH     32
#define HDIM   128
#define DIM    4096
#define NQ     (SEGN*RQ)     // 2048
#define NTOK   (SEGN*LSEG)   // 16384
#define KVW    (2*NH*HDIM)   // 8192
#define EPS    1e-5f

#if defined(__CUDA_ARCH_FEAT_SM103_ALL) || defined(__CUDA_ARCH_FEAT_SM100_ALL)
#define TC_OK 1
#else
#define TC_OK 0
#endif

// ---------------- scratch ----------------
__device__ __align__(128) float g_queries[(size_t)NQ*DIM];
__device__ __align__(128) float g_q[(size_t)NQ*DIM];
__device__ __align__(128) __half g_kv_h[(size_t)NTOK*KVW];
__device__ __align__(128) float g_tmp[(size_t)NQ*DIM];

__device__ __align__(128) __half g_a_hi[(size_t)NTOK*DIM];
__device__ __align__(128) __half g_a_lo[(size_t)NTOK*DIM];
__device__ __align__(128) __half g_bkv[(size_t)KVW*DIM];
__device__ __align__(128) __half g_bq[(size_t)DIM*DIM];
__device__ __align__(128) __half g_bo[(size_t)DIM*DIM];
__device__ __align__(128) __half g_qn_hi[(size_t)NQ*DIM];
__device__ __align__(128) __half g_qn_lo[(size_t)NQ*DIM];
__device__ __align__(128) __half g_o_hi[(size_t)NQ*DIM];
__device__ __align__(128) __half g_o_lo[(size_t)NQ*DIM];

// ---------------- generic helpers ----------------
__device__ __forceinline__ uint32_t s2u(const void* p) {
    return (uint32_t)__cvta_generic_to_shared(p);
}
__device__ __forceinline__ void mbar_init(uint32_t a, uint32_t cnt) {
    asm volatile("mbarrier.init.shared.b64 [%0], %1;" :: "r"(a), "r"(cnt) : "memory");
}
__device__ __forceinline__ void mbar_wait(uint32_t a, uint32_t phase) {
    uint32_t done;
    do {
        asm volatile("{\n\t.reg .pred p;\n\t"
                     "mbarrier.try_wait.parity.shared::cta.b64 p, [%1], %2, 0x989680;\n\t"
                     "selp.b32 %0, 1, 0, p;\n\t}"
                     : "=r"(done) : "r"(a), "r"(phase) : "memory");
    } while (!done);
}
__device__ __forceinline__ void mbar_expect_tx(uint32_t a, uint32_t bytes) {
    asm volatile("mbarrier.arrive.expect_tx.shared.b64 _, [%0], %1;"
                 :: "r"(a), "r"(bytes) : "memory");
}
__device__ __forceinline__ void tma_load_2d(uint32_t dst, const void* map,
                                            int cx, int cy, uint32_t bar) {
    asm volatile("cp.async.bulk.tensor.2d.shared::cta.global.tile.mbarrier::complete_tx::bytes "
                 "[%0], [%1, {%2, %3}], [%4];"
                 :: "r"(dst), "l"(map), "r"(cx), "r"(cy), "r"(bar) : "memory");
}
// fp16 mma
__device__ __forceinline__ void mma16816h(float* c, const uint32_t* a, uint32_t b0, uint32_t b1) {
    asm volatile("mma.sync.aligned.m16n8k16.row.col.f32.f16.f16.f32 "
                 "{%0,%1,%2,%3}, {%4,%5,%6,%7}, {%8,%9}, {%0,%1,%2,%3};"
                 : "+f"(c[0]), "+f"(c[1]), "+f"(c[2]), "+f"(c[3])
                 : "r"(a[0]), "r"(a[1]), "r"(a[2]), "r"(a[3]), "r"(b0), "r"(b1));
}
// split float2 -> packed fp16x2 hi + lo
__device__ __forceinline__ void split2h(float2 v, uint32_t& hi, uint32_t& lo) {
    __half hx = __float2half_rn(v.x), hy = __float2half_rn(v.y);
    __half2 hp = __halves2half2(hx, hy);
    hi = *(uint32_t*)&hp;
    __half2 lp = __halves2half2(
        __float2half_rn(v.x - __half2float(hx)),
        __float2half_rn(v.y - __half2float(hy)));
    lo = *(uint32_t*)&lp;
}
// float2 -> packed fp16x2 (single)
__device__ __forceinline__ uint32_t pack2h(float2 v) {
    __half2 hp = __halves2half2(__float2half_rn(v.x), __float2half_rn(v.y));
    return *(uint32_t*)&hp;
}

#if TC_OK
// ---------------- tcgen05 helpers ----------------
__device__ __forceinline__ void tc_alloc(uint32_t smem_dst, uint32_t ncols) {
    asm volatile("tcgen05.alloc.cta_group::1.sync.aligned.shared::cta.b32 [%0], %1;"
                 :: "r"(smem_dst), "r"(ncols) : "memory");
}
__device__ __forceinline__ void tc_dealloc(uint32_t tmem, uint32_t ncols) {
    asm volatile("tcgen05.relinquish_alloc_permit.cta_group::1.sync.aligned;");
    asm volatile("tcgen05.dealloc.cta_group::1.sync.aligned.b32 %0, %1;" :: "r"(tmem), "r"(ncols));
}
__device__ __forceinline__ void tc_commit(uint32_t bar) {
    asm volatile("tcgen05.commit.cta_group::1.mbarrier::arrive::one.shared::cluster.b64 [%0];"
                 :: "r"(bar) : "memory");
}
__device__ __forceinline__ void tc_mma_f16_ss(uint32_t d, uint64_t ad, uint64_t bd,
                                              uint32_t idesc, uint32_t accum) {
    asm volatile("{\n\t.reg .pred p;\n\t"
                 "setp.ne.u32 p, %4, 0;\n\t"
                 "tcgen05.mma.cta_group::1.kind::f16 [%0], %1, %2, %3, {%5, %5, %5, %5}, p;\n\t}"
                 :: "r"(d), "l"(ad), "l"(bd), "r"(idesc), "r"(accum), "r"(0u) : "memory");
}
__device__ __forceinline__ void tc_fence_after() {
    asm volatile("tcgen05.fence::after_thread_sync;" ::: "memory");
}
#define LDTM_X32(r, addr) \
    asm volatile("tcgen05.ld.sync.aligned.32x32b.x32.b32 " \
        "{%0, %1, %2, %3, %4, %5, %6, %7, %8, %9, %10, %11, %12, %13, %14, %15, " \
        "%16, %17, %18, %19, %20, %21, %22, %23, %24, %25, %26, %27, %28, %29, %30, %31}, [%32];" \
        : "=r"((r)[0]), "=r"((r)[1]), "=r"((r)[2]), "=r"((r)[3]), \
          "=r"((r)[4]), "=r"((r)[5]), "=r"((r)[6]), "=r"((r)[7]), \
          "=r"((r)[8]), "=r"((r)[9]), "=r"((r)[10]), "=r"((r)[11]), \
          "=r"((r)[12]), "=r"((r)[13]), "=r"((r)[14]), "=r"((r)[15]), \
          "=r"((r)[16]), "=r"((r)[17]), "=r"((r)[18]), "=r"((r)[19]), \
          "=r"((r)[20]), "=r"((r)[21]), "=r"((r)[22]), "=r"((r)[23]), \
          "=r"((r)[24]), "=r"((r)[25]), "=r"((r)[26]), "=r"((r)[27]), \
          "=r"((r)[28]), "=r"((r)[29]), "=r"((r)[30]), "=r"((r)[31]) \
        : "r"(addr))
__device__ __forceinline__ void tc_wait_ld() {
    asm volatile("tcgen05.wait::ld.sync.aligned;" ::: "memory");
}
// SW64 K-major descriptor
static __device__ __forceinline__ uint64_t make_desc64(uint32_t addr) {
    const uint64_t base = (uint64_t(4) << 61) | (uint64_t(1) << 46) |
                          (uint64_t(32) << 32) | (uint64_t(1) << 16);
    return base | ((uint64_t)(addr >> 4) & 0x3FFFull);
}
#endif

// ---------------- weight transpose -> fp16 ----------------
__global__ void wsplit_kernel(const float* __restrict__ in,
                              __half* __restrict__ out,
                              int Kdim, int Ndim) {
    __shared__ float t[32][33];
    int n0 = blockIdx.x * 32, k0 = blockIdx.y * 32;
    int tx = threadIdx.x, ty = threadIdx.y;
    for (int r = ty; r < 32; r += 8)
        t[r][tx] = in[(size_t)(k0 + r) * Ndim + n0 + tx];
    __syncthreads();
    for (int r = ty; r < 32; r += 8)
        out[(size_t)(n0 + r) * Kdim + k0 + tx] = __float2half_rn(t[tx][r]);
}

// ---------------- fused: x split (fp16 hi/lo) + pooling + attention rmsnorm ----------------
__global__ void pool_rmsnorm_kernel(const float* __restrict__ x,
                                    const float* __restrict__ w) {
    int row = blockIdx.x;
    int tid = threadIdx.x;
    const float* base = x + (size_t)row * POOLN * DIM;
    float local = 0.f;
    #pragma unroll
    for (int i = 0; i < DIM / 512; i++) {
        int d = (tid + i * 256) * 2;
        float2 s = make_float2(0.f, 0.f);
        #pragma unroll
        for (int p = 0; p < POOLN; p++) {
            float2 v = *(const float2*)&base[(size_t)p*DIM + d];
            uint32_t hi, lo; split2h(v, hi, lo);
            size_t o = (size_t)(row * POOLN + p) * DIM + d;
            *(uint32_t*)&g_a_hi[o] = hi;
            *(uint32_t*)&g_a_lo[o] = lo;
            s.x += v.x; s.y += v.y;
        }
        s.x *= (1.0f / POOLN); s.y *= (1.0f / POOLN);
        *(float2*)&g_queries[(size_t)row*DIM + d] = s;
        local += s.x * s.x + s.y * s.y;
    }
    __shared__ float red[256];
    red[tid] = local; __syncthreads();
    for (int st = 128; st > 0; st >>= 1) {
        if (tid < st) red[tid] += red[tid + st];
        __syncthreads();
    }
    float rstd = rsqrtf(red[0] / DIM + EPS);
    #pragma unroll
    for (int i = 0; i < DIM / 512; i++) {
        int d = (tid + i * 256) * 2;
        float2 qv = *(float2*)&g_queries[(size_t)row*DIM + d];
        float2 wv = *(const float2*)&w[d];
        float2 v = make_float2(qv.x * rstd * wv.x, qv.y * rstd * wv.y);
        uint32_t hi, lo; split2h(v, hi, lo);
        *(uint32_t*)&g_qn_hi[(size_t)row*DIM + d] = hi;
        *(uint32_t*)&g_qn_lo[(size_t)row*DIM + d] = lo;
    }
}

// ---------------- fp16x2 GEMM: C[M,N] = (Ah+Al)[M,K] @ B[N,K]^T ----------------
#define BM 256
#define BN 256
#define GK 4096
#define KITERS (GK/32)
#define A_TILE_B 8192u
#define B_TILE_B 16384u
#define STAGE_BYTES (4u*A_TILE_B + B_TILE_B)   // 49152
#define NSTAGE 4
#define GEMM_SMEM (NSTAGE*STAGE_BYTES + 1024)

__global__ __launch_bounds__(256, 1)
void gemm3_kernel(int N, int nbm, int nbn, int half_out, int m_base,
                  const __grid_constant__ CUtensorMap mAh,
                  const __grid_constant__ CUtensorMap mAl,
                  const __grid_constant__ CUtensorMap mB,
                  const __half* __restrict__ Ah,
                  const __half* __restrict__ Al,
                  const __half* __restrict__ B,
                  float* __restrict__ C,
                  __half* __restrict__ Ch) {
    extern __shared__ char smraw[];
    char* smp = (char*)((((uintptr_t)smraw) + 1023) & ~(uintptr_t)1023);
    int tid = threadIdx.x;

    const int GM = 16;
    int bid = blockIdx.x;
    int group = bid / (GM * nbn);
    int first_m = group * GM;
    int gsz = min(nbm - first_m, GM);
    int pm = first_m + (bid % gsz);
    int pn = (bid % (GM * nbn)) / gsz;
    int m0 = m_base + pm * BM, n0 = pn * BN;

#if TC_OK
    uint32_t sb0 = s2u(smp);
    __shared__ __align__(8) unsigned long long full_b[NSTAGE], empty_b[NSTAGE], fin_b;
    __shared__ uint32_t tmem_ptr_sh;

    uint32_t full_a[NSTAGE], empty_a[NSTAGE], fin_a;
    #pragma unroll
    for (int i = 0; i < NSTAGE; i++) {
        full_a[i] = s2u(&full_b[i]);
        empty_a[i] = s2u(&empty_b[i]);
    }
    fin_a = s2u(&fin_b);

    if (tid < 32) tc_alloc(s2u(&tmem_ptr_sh), 512);
    if (tid == 0) {
        #pragma unroll
        for (int i = 0; i < NSTAGE; i++) {
            mbar_init(full_a[i], 1);
            mbar_init(empty_a[i], 1);
        }
        mbar_init(fin_a, 1);
    }
    __syncthreads();
    uint32_t tmem = tmem_ptr_sh;

    const uint32_t idesc = (1u<<4) | ((BN/8)<<17) | (8u<<24);

    if (tid == 32) {
        for (int it = 0; it < KITERS; it++) {
            int s = it % NSTAGE;
            uint32_t ph = ((it / NSTAGE) & 1) ^ 1u;
            mbar_wait(empty_a[s], ph);
            int k0 = it * 32;
            uint32_t sb = sb0 + s * STAGE_BYTES;
            uint32_t bar = full_a[s];
            mbar_expect_tx(bar, STAGE_BYTES);
            tma_load_2d(sb,                &mAh, k0, m0,       bar);
            tma_load_2d(sb + A_TILE_B,     &mAl, k0, m0,       bar);
            tma_load_2d(sb + 2u*A_TILE_B,  &mAh, k0, m0 + 128, bar);
            tma_load_2d(sb + 3u*A_TILE_B,  &mAl, k0, m0 + 128, bar);
            tma_load_2d(sb + 4u*A_TILE_B,  &mB,  k0, n0,       bar);
        }
    } else if (tid == 0) {
        for (int it = 0; it < KITERS; it++) {
            int s = it % NSTAGE;
            uint32_t ph = (it / NSTAGE) & 1;
            mbar_wait(full_a[s], ph);
            uint32_t sb = sb0 + s * STAGE_BYTES;
            uint64_t a0h = make_desc64(sb);
            uint64_t a0l = make_desc64(sb + A_TILE_B);
            uint64_t a1h = make_desc64(sb + 2u*A_TILE_B);
            uint64_t a1l = make_desc64(sb + 3u*A_TILE_B);
            uint64_t bd  = make_desc64(sb + 4u*A_TILE_B);
            #pragma unroll
            for (int ks = 0; ks < 2; ks++) {
                uint32_t acc = (it > 0 || ks > 0) ? 1u : 0u;
                uint64_t o = ks * 2;
                tc_mma_f16_ss(tmem,       a0h + o, bd + o, idesc, acc);
                tc_mma_f16_ss(tmem + 256, a1h + o, bd + o, idesc, acc);
                tc_mma_f16_ss(tmem,       a0l + o, bd + o, idesc, 1u);
                tc_mma_f16_ss(tmem + 256, a1l + o, bd + o, idesc, 1u);
            }
            tc_commit(empty_a[s]);
        }
        tc_commit(fin_a);
    }

    __syncthreads();
    mbar_wait(fin_a, 0);
    tc_fence_after();

    float* stg = (float*)smp;
    int w = tid >> 5, lane = tid & 31;
    #pragma unroll
    for (int half = 0; half < 2; half++) {
        if (w < 4) {
            for (int ch = 0; ch < 8; ch++) {
                uint32_t r[32];
                LDTM_X32(r, tmem + half * 256 + ch * 32);
                tc_wait_ld();
                #pragma unroll
                for (int j = 0; j < 32; j++)
                    stg[(size_t)(w * 32 + lane) * 260 + ch * 32 + j] = __uint_as_float(r[j]);
            }
        }
        __syncthreads();
        int c4 = (tid & 63) * 4;
        if (half_out) {
            for (int rr = tid >> 6; rr < 128; rr += 4) {
                float4 v = *(float4*)&stg[(size_t)rr * 260 + c4];
                uint32_t p0 = pack2h(make_float2(v.x, v.y));
                uint32_t p1 = pack2h(make_float2(v.z, v.w));
                *(uint2*)&Ch[(size_t)(m0 + half * 128 + rr) * N + n0 + c4] =
                    make_uint2(p0, p1);
            }
        } else {
            for (int rr = tid >> 6; rr < 128; rr += 4) {
                float4 v = *(float4*)&stg[(size_t)rr * 260 + c4];
                *(float4*)&C[(size_t)(m0 + half * 128 + rr) * N + n0 + c4] = v;
            }
        }
        __syncthreads();
    }
    if (tid < 32) tc_dealloc(tmem, 512);
#else
    // mma.sync fp16x2 fallback (bare sm_103; not selected on GB300)
    __half* sAh = (__half*)smp;
    __half* sAl = sAh + 128 * 40;
    __half* sB  = sAl + 128 * 40;

    int lane = tid & 31, w = tid >> 5;
    int wm = w & 3, wn = w >> 2;

    for (int mh = 0; mh < 2; mh++)
    for (int nh = 0; nh < 2; nh++) {
        int m0h = m0 + mh * 128;
        int n0h = n0 + nh * 128;
        float acc[2][4][4];
        #pragma unroll
        for (int mi = 0; mi < 2; mi++)
            #pragma unroll
            for (int ni = 0; ni < 4; ni++)
                #pragma unroll
                for (int j = 0; j < 4; j++) acc[mi][ni][j] = 0.f;

        for (int k0 = 0; k0 < GK; k0 += 32) {
            __syncthreads();
            for (int cid = tid; cid < 512; cid += 256) {
                int r = cid >> 2, c = cid & 3;
                *(uint4*)&sAh[r*40 + c*8] = *(const uint4*)&Ah[(size_t)(m0h+r)*GK + k0 + c*8];
                *(uint4*)&sAl[r*40 + c*8] = *(const uint4*)&Al[(size_t)(m0h+r)*GK + k0 + c*8];
                *(uint4*)&sB [r*40 + c*8] = *(const uint4*)&B [(size_t)(n0h+r)*GK + k0 + c*8];
            }
            __syncthreads();
            #pragma unroll
            for (int ks = 0; ks < 2; ks++) {
                int kc = (lane & 3) * 2 + ks * 16;
                uint32_t ah[2][4], al[2][4];
                #pragma unroll
                for (int mi = 0; mi < 2; mi++) {
                    int r = wm * 32 + mi * 16 + (lane >> 2);
                    ah[mi][0] = *(uint32_t*)&sAh[r*40 + kc];
                    ah[mi][1] = *(uint32_t*)&sAh[(r+8)*40 + kc];
                    ah[mi][2] = *(uint32_t*)&sAh[r*40 + kc + 8];
                    ah[mi][3] = *(uint32_t*)&sAh[(r+8)*40 + kc + 8];
                    al[mi][0] = *(uint32_t*)&sAl[r*40 + kc];
                    al[mi][1] = *(uint32_t*)&sAl[(r+8)*40 + kc];
                    al[mi][2] = *(uint32_t*)&sAl[r*40 + kc + 8];
                    al[mi][3] = *(uint32_t*)&sAl[(r+8)*40 + kc + 8];
                }
                #pragma unroll
                for (int ni = 0; ni < 4; ni++) {
                    int nr = wn * 64 + ni * 8 + (lane >> 2);
                    uint32_t b0 = *(uint32_t*)&sB[nr*40 + kc];
                    uint32_t b1 = *(uint32_t*)&sB[nr*40 + kc + 8];
                    #pragma unroll
                    for (int mi = 0; mi < 2; mi++) {
                        mma16816h(acc[mi][ni], ah[mi], b0, b1);
                        mma16816h(acc[mi][ni], al[mi], b0, b1);
                    }
                }
            }
        }
        #pragma unroll
        for (int mi = 0; mi < 2; mi++)
            #pragma unroll
            for (int ni = 0; ni < 4; ni++) {
                int r = m0h + wm * 32 + mi * 16 + (lane >> 2);
                int c = n0h + wn * 64 + ni * 8 + (lane & 3) * 2;
                if (half_out) {
                    *(uint32_t*)&Ch[(size_t)r * N + c] =
                        pack2h(make_float2(acc[mi][ni][0], acc[mi][ni][1]));
                    *(uint32_t*)&Ch[(size_t)(r+8) * N + c] =
                        pack2h(make_float2(acc[mi][ni][2], acc[mi][ni][3]));
                } else {
                    *(float2*)&C[(size_t)r * N + c] = make_float2(acc[mi][ni][0], acc[mi][ni][1]);
                    *(float2*)&C[(size_t)(r+8) * N + c] = make_float2(acc[mi][ni][2], acc[mi][ni][3]);
                }
            }
    }
#endif
}

// ---------------- tensor-core attention: 64-token chunks, seg_base param ----------------
#define SROW 514
#define QROW 132
#define VTROW 66
#define OFF_QH 65792
#define OFF_QL (OFF_QH + 8448)
#define OFF_K  (OFF_QL + 8448)
#define OFF_RI (OFF_K + 16896)
#define ATT2_SMEM (OFF_RI + 128)

__global__ __launch_bounds__(256, 2)
void attention2_kernel(int seg_base) {
    extern __shared__ char asmem[];
    float* sS = (float*)asmem;
    __half* sQh = (__half*)(asmem + OFF_QH);
    __half* sQl = (__half*)(asmem + OFF_QL);
    __half* sK  = (__half*)(asmem + OFF_K);
    float* rinv = (float*)(asmem + OFF_RI);

    int bid = blockIdx.x;
    int rt = bid & 1;
    int h  = (bid >> 1) & 31;
    int s  = seg_base + (bid >> 6);
    int q0 = s * RQ + rt * 32;
    int t0 = s * LSEG;

    int tid = threadIdx.x;
    int w = tid >> 5, lane = tid & 31;
    int wm = w & 1;
    int wn = w >> 1;
    int lr = lane >> 2, lc = lane & 3;

    // load Q (32 x 128) -> fp16 hi/lo smem
    for (int i = tid; i < 32 * 64; i += 256) {
        int r = i >> 6, c2 = (i & 63) * 2;
        float2 v = *(float2*)&g_q[(size_t)(q0 + r) * DIM + h * HDIM + c2];
        uint32_t hi, lo; split2h(v, hi, lo);
        *(uint32_t*)&sQh[r * QROW + c2] = hi;
        *(uint32_t*)&sQl[r * QROW + c2] = lo;
    }

    const float scale = rsqrtf((float)HDIM);

    // ---- phase 1: S = scale * Q K^T  (8 chunks of 64 tokens) ----
    for (int ck = 0; ck < 8; ck++) {
        __syncthreads();
        for (int i = tid; i < 64 * 32; i += 256) {
            int r = i >> 5, c4 = (i & 31) * 4;
            uint2 v = *(uint2*)&g_kv_h[(size_t)(t0 + ck * 64 + r) * KVW + h * HDIM + c4];
            *(uint2*)&sK[r * QROW + c4] = v;
        }
        __syncthreads();

        float acc[2][4];
        #pragma unroll
        for (int nt = 0; nt < 2; nt++)
            #pragma unroll
            for (int j = 0; j < 4; j++) acc[nt][j] = 0.f;
        int r0 = wm * 16 + lr;
        #pragma unroll
        for (int kk = 0; kk < 8; kk++) {
            int k0 = kk * 16;
            uint32_t ah[4], al[4];
            ah[0] = *(uint32_t*)&sQh[r0 * QROW + k0 + lc * 2];
            ah[1] = *(uint32_t*)&sQh[(r0 + 8) * QROW + k0 + lc * 2];
            ah[2] = *(uint32_t*)&sQh[r0 * QROW + k0 + 8 + lc * 2];
            ah[3] = *(uint32_t*)&sQh[(r0 + 8) * QROW + k0 + 8 + lc * 2];
            al[0] = *(uint32_t*)&sQl[r0 * QROW + k0 + lc * 2];
            al[1] = *(uint32_t*)&sQl[(r0 + 8) * QROW + k0 + lc * 2];
            al[2] = *(uint32_t*)&sQl[r0 * QROW + k0 + 8 + lc * 2];
            al[3] = *(uint32_t*)&sQl[(r0 + 8) * QROW + k0 + 8 + lc * 2];
            #pragma unroll
            for (int nt = 0; nt < 2; nt++) {
                int nb = wn * 16 + nt * 8;
                uint32_t b0 = *(uint32_t*)&sK[(nb + lr) * QROW + k0 + lc * 2];
                uint32_t b1 = *(uint32_t*)&sK[(nb + lr) * QROW + k0 + 8 + lc * 2];
                mma16816h(acc[nt], ah, b0, b1);
                mma16816h(acc[nt], al, b0, b1);
            }
        }
        #pragma unroll
        for (int nt = 0; nt < 2; nt++) {
            int col = ck * 64 + wn * 16 + nt * 8 + lc * 2;
            *(float2*)&sS[r0 * SROW + col] = make_float2(acc[nt][0] * scale, acc[nt][1] * scale);
            *(float2*)&sS[(r0 + 8) * SROW + col] = make_float2(acc[nt][2] * scale, acc[nt][3] * scale);
        }
    }
    __syncthreads();

    // ---- phase 2: softmax ----
    for (int j = 0; j < 4; j++) {
        int r = w * 4 + j;
        float m = -1e30f;
        for (int i = lane; i < LSEG; i += 32) m = fmaxf(m, sS[r * SROW + i]);
        #pragma unroll
        for (int o = 16; o; o >>= 1) m = fmaxf(m, __shfl_xor_sync(0xffffffffu, m, o));
        float sum = 0.f;
        for (int i = lane; i < LSEG; i += 32) {
            float e = __expf(sS[r * SROW + i] - m);
            sS[r * SROW + i] = e;
            sum += e;
        }
        #pragma unroll
        for (int o = 16; o; o >>= 1) sum += __shfl_xor_sync(0xffffffffu, sum, o);
        if (lane == 0) rinv[r] = 1.0f / sum;
    }

    // ---- phase 3: O = P V (8 chunks of 64 tokens) ----
    float oacc[4][4];
    #pragma unroll
    for (int nt = 0; nt < 4; nt++)
        #pragma unroll
        for (int j = 0; j < 4; j++) oacc[nt][j] = 0.f;

    for (int ck = 0; ck < 8; ck++) {
        __syncthreads();
        for (int i = tid; i < 64 * 64; i += 256) {
            int t = i >> 6, hd2 = (i & 63) * 2;
            uint32_t v = *(uint32_t*)&g_kv_h[(size_t)(t0 + ck * 64 + t) * KVW
                                             + NH * HDIM + h * HDIM + hd2];
            __half2 hv = *(__half2*)&v;
            sK[hd2 * VTROW + t] = __low2half(hv);
            sK[(hd2 + 1) * VTROW + t] = __high2half(hv);
        }
        __syncthreads();

        #pragma unroll
        for (int kk = 0; kk < 4; kk++) {
            int kt = ck * 64 + kk * 16;
            int kl = kk * 16;
            int r0 = wm * 16 + lr;
            float2 p0 = *(float2*)&sS[r0 * SROW + kt + lc * 2];
            float2 p1 = *(float2*)&sS[(r0 + 8) * SROW + kt + lc * 2];
            float2 p2 = *(float2*)&sS[r0 * SROW + kt + 8 + lc * 2];
            float2 p3 = *(float2*)&sS[(r0 + 8) * SROW + kt + 8 + lc * 2];
            uint32_t ah[4], al[4];
            split2h(p0, ah[0], al[0]);
            split2h(p1, ah[1], al[1]);
            split2h(p2, ah[2], al[2]);
            split2h(p3, ah[3], al[3]);
            #pragma unroll
            for (int nt = 0; nt < 4; nt++) {
                int hd0 = wn * 32 + nt * 8;
                uint32_t b0 = *(uint32_t*)&sK[(hd0 + lr) * VTROW + kl + lc * 2];
                uint32_t b1 = *(uint32_t*)&sK[(hd0 + lr) * VTROW + kl + 8 + lc * 2];
                mma16816h(oacc[nt], ah, b0, b1);
                mma16816h(oacc[nt], al, b0, b1);
            }
        }
    }

    // ---- writeback ----
    {
        int r0 = wm * 16 + lr;
        float ri0 = rinv[r0], ri1 = rinv[r0 + 8];
        #pragma unroll
        for (int nt = 0; nt < 4; nt++) {
            int c0 = h * HDIM + wn * 32 + nt * 8 + lc * 2;
            uint32_t hi, lo;
            split2h(make_float2(oacc[nt][0] * ri0, oacc[nt][1] * ri0), hi, lo);
            *(uint32_t*)&g_o_hi[(size_t)(q0 + r0) * DIM + c0] = hi;
            *(uint32_t*)&g_o_lo[(size_t)(q0 + r0) * DIM + c0] = lo;
            split2h(make_float2(oacc[nt][2] * ri1, oacc[nt][3] * ri1), hi, lo);
            *(uint32_t*)&g_o_hi[(size_t)(q0 + r0 + 8) * DIM + c0] = hi;
            *(uint32_t*)&g_o_lo[(size_t)(q0 + r0 + 8) * DIM + c0] = lo;
        }
    }
}

// ---------------- final: residual + rmsnorm ----------------
__global__ void final_kernel(const float* __restrict__ w, float* __restrict__ out) {
    int row = blockIdx.x;
    int tid = threadIdx.x;
    float vals[DIM / 256];
    float local = 0.f;
    #pragma unroll
    for (int i = 0; i < DIM / 256; i++) {
        int d = tid + i * 256;
        float v = g_tmp[(size_t)row * DIM + d] + g_queries[(size_t)row * DIM + d];
        vals[i] = v;
        local += v * v;
    }
    __shared__ float red[256];
    red[tid] = local; __syncthreads();
    for (int st = 128; st > 0; st >>= 1) {
        if (tid < st) red[tid] += red[tid + st];
        __syncthreads();
    }
    float rstd = rsqrtf(red[0] / DIM + EPS);
    #pragma unroll
    for (int i = 0; i < DIM / 256; i++) {
        int d = tid + i * 256;
        out[(size_t)row * DIM + d] = vals[i] * rstd * w[d];
    }
}

// ---------------- host: tensormap encode ----------------
typedef CUresult (*PFN_tmEncode)(CUtensorMap*, CUtensorMapDataType, cuuint32_t, void*,
                                 const cuuint64_t*, const cuuint64_t*, const cuuint32_t*,
                                 const cuuint32_t*, CUtensorMapInterleave, CUtensorMapSwizzle,
                                 CUtensorMapL2promotion, CUtensorMapFloatOOBfill);

static PFN_tmEncode get_encoder() {
    void* p = nullptr;
#if CUDART_VERSION >= 12050
    cudaDriverEntryPointQueryResult qr;
    cudaGetDriverEntryPointByVersion("cuTensorMapEncodeTiled", &p, 12000,
                                     cudaEnableDefault, &qr);
#else
    cudaGetDriverEntryPoint("cuTensorMapEncodeTiled", &p, cudaEnableDefault);
#endif
    return (PFN_tmEncode)p;
}

static void enc2d(PFN_tmEncode enc, CUtensorMap* m, void* base,
                  uint64_t rows, uint32_t boxRows) {
    cuuint64_t dims[2]    = {GK, rows};
    cuuint64_t strides[1] = {GK * 2};
    cuuint32_t box[2]     = {32, boxRows};
    cuuint32_t es[2]      = {1, 1};
    enc(m, CU_TENSOR_MAP_DATA_TYPE_FLOAT16, 2, base, dims, strides, box, es,
        CU_TENSOR_MAP_INTERLEAVE_NONE, CU_TENSOR_MAP_SWIZZLE_64B,
        CU_TENSOR_MAP_L2_PROMOTION_L2_128B, CU_TENSOR_MAP_FLOAT_OOB_FILL_NONE);
}

// ---------------- launch ----------------
extern "C" void kernel_launch(void* const* d_in, const int* in_sizes, int n_in,
                              void* d_out, int out_size) {
    const float* x      = (const float*)d_in[0];
    const float* attn_w = (const float*)d_in[1];
    const float* wq     = (const float*)d_in[2];
    const float* wkv    = (const float*)d_in[3];
    const float* wo     = (const float*)d_in[4];
    const float* out_w  = (const float*)d_in[5];
    float* out = (float*)d_out;

    float *pq, *ptmp;
    __half *pkvh, *pah, *pal, *pbkv, *pbq, *pbo, *pqnh, *pqnl, *poh, *pol;
    cudaGetSymbolAddress((void**)&pq,   g_q);
    cudaGetSymbolAddress((void**)&pkvh, g_kv_h);
    cudaGetSymbolAddress((void**)&ptmp, g_tmp);
    cudaGetSymbolAddress((void**)&pah,  g_a_hi);
    cudaGetSymbolAddress((void**)&pal,  g_a_lo);
    cudaGetSymbolAddress((void**)&pbkv, g_bkv);
    cudaGetSymbolAddress((void**)&pbq,  g_bq);
    cudaGetSymbolAddress((void**)&pbo,  g_bo);
    cudaGetSymbolAddress((void**)&pqnh, g_qn_hi);
    cudaGetSymbolAddress((void**)&pqnl, g_qn_lo);
    cudaGetSymbolAddress((void**)&poh,  g_o_hi);
    cudaGetSymbolAddress((void**)&pol,  g_o_lo);

    PFN_tmEncode enc = get_encoder();
    CUtensorMap mQA_h, mQA_l, mQB;
    CUtensorMap mKA_h, mKA_l, mKB;
    CUtensorMap mOA_h, mOA_l, mOB;
    enc2d(enc, &mQA_h, pqnh, NQ,   128);
    enc2d(enc, &mQA_l, pqnl, NQ,   128);
    enc2d(enc, &mQB,   pbq,  DIM,  256);
    enc2d(enc, &mKA_h, pah,  NTOK, 128);
    enc2d(enc, &mKA_l, pal,  NTOK, 128);
    enc2d(enc, &mKB,   pbkv, KVW,  256);
    enc2d(enc, &mOA_h, poh,  NQ,   128);
    enc2d(enc, &mOA_l, pol,  NQ,   128);
    enc2d(enc, &mOB,   pbo,  DIM,  256);

    cudaFuncSetAttribute(attention2_kernel,
                         cudaFuncAttributeMaxDynamicSharedMemorySize, (int)ATT2_SMEM);
    cudaFuncSetAttribute(gemm3_kernel,
                         cudaFuncAttributeMaxDynamicSharedMemorySize, (int)GEMM_SMEM);

    // side stream + events (created once; host objects only)
    static cudaStream_t s1 = nullptr;
    static cudaEvent_t evR = nullptr, evW = nullptr, evPool = nullptr;
    static cudaEvent_t evKV[4] = {nullptr, nullptr, nullptr, nullptr};
    static cudaEvent_t evA01 = nullptr, evO0 = nullptr;
    if (s1 == nullptr) {
        cudaStreamCreateWithFlags(&s1, cudaStreamNonBlocking);
        cudaEventCreateWithFlags(&evR,    cudaEventDisableTiming);
        cudaEventCreateWithFlags(&evW,    cudaEventDisableTiming);
        cudaEventCreateWithFlags(&evPool, cudaEventDisableTiming);
        for (int i = 0; i < 4; i++)
            cudaEventCreateWithFlags(&evKV[i], cudaEventDisableTiming);
        cudaEventCreateWithFlags(&evA01, cudaEventDisableTiming);
        cudaEventCreateWithFlags(&evO0,  cudaEventDisableTiming);
    }

    // fork: weight transposes on s1, pooling on main
    cudaEventRecord(evR, 0);
    cudaStreamWaitEvent(s1, evR, 0);
    wsplit_kernel<<<dim3(KVW/32, DIM/32), dim3(32,8), 0, s1>>>(wkv, pbkv, DIM, KVW);
    wsplit_kernel<<<dim3(DIM/32, DIM/32), dim3(32,8), 0, s1>>>(wq, pbq, DIM, DIM);
    wsplit_kernel<<<dim3(DIM/32, DIM/32), dim3(32,8), 0, s1>>>(wo, pbo, DIM, DIM);
    cudaEventRecord(evW, s1);

    pool_rmsnorm_kernel<<<NQ, 256>>>(x, attn_w);
    cudaEventRecord(evPool, 0);

    // kv = x @ wkv on s1, split into four M-quarters (fp16 output)
    cudaStreamWaitEvent(s1, evPool, 0);
    const int MQ = NTOK / 4;                 // 4096 tokens per quarter
    for (int i = 0; i < 4; i++) {
        gemm3_kernel<<<(MQ/BM)*(KVW/BN), 256, GEMM_SMEM, s1>>>(KVW, MQ/BM, KVW/BN, 1, i*MQ,
            mKA_h, mKA_l, mKB, pah, pal, pbkv, nullptr, pkvh);
        cudaEventRecord(evKV[i], s1);
    }

    // q = qn @ wq on main (fp32 output)
    cudaStreamWaitEvent(0, evW, 0);
    gemm3_kernel<<<(NQ/BM)*(DIM/BN), 256, GEMM_SMEM>>>(DIM, NQ/BM, DIM/BN, 0, 0,
        mQA_h, mQA_l, mQB, pqnh, pqnl, pbq, pq, nullptr);

    // attention quarters on main; quarter i waits kv quarter i
    const int SQ = SEGN / 4;                 // 8 segments per quarter
    for (int i = 0; i < 4; i++) {
        cudaStreamWaitEvent(0, evKV[i], 0);
        attention2_kernel<<<SQ * NH * 2, 256, ATT2_SMEM>>>(i * SQ);
        if (i == 1) cudaEventRecord(evA01, 0);
    }

    // o-GEMM half 0 (q rows 0..NQ/2) on s1 overlaps attention quarters 2-3
    cudaStreamWaitEvent(s1, evA01, 0);
    gemm3_kernel<<<(NQ/2/BM)*(DIM/BN), 256, GEMM_SMEM, s1>>>(DIM, NQ/2/BM, DIM/BN, 0, 0,
        mOA_h, mOA_l, mOB, poh, pol, pbo, ptmp, nullptr);
    cudaEventRecord(evO0, s1);

    // o-GEMM half 1 on main (after attention quarter 3, program order)
    gemm3_kernel<<<(NQ/2/BM)*(DIM/BN), 256, GEMM_SMEM>>>(DIM, NQ/2/BM, DIM/BN, 0, NQ/2,
        mOA_h, mOA_l, mOB, poh, pol, pbo, ptmp, nullptr);

    // final join
    cudaStreamWaitEvent(0, evO0, 0);
    final_kernel<<<NQ, 256>>>(out_w, out);
}

// round 15
// speedup vs baseline: 1.0091x; 1.0091x over previous
#include <cuda_runtime.h>
#include <cuda.h>
#include <cuda_bf16.h>
#include <cuda_fp16.h>
#include <math.h>
#include <stdint.h>

// ---------------- problem constants ----------------
#define SEGN   32
#define LSEG   512
#define RQ     64
#define POOLN  8
#define NH     32
#define HDIM   128
#define DIM    4096
#define NQ     (SEGN*RQ)     // 2048
#define NTOK   (SEGN*LSEG)   // 16384
#define KVW    (2*NH*HDIM)   // 8192
#define EPS    1e-5f

#if defined(__CUDA_ARCH_FEAT_SM103_ALL) || defined(__CUDA_ARCH_FEAT_SM100_ALL)
#define TC_OK 1
#else
#define TC_OK 0
#endif

// ---------------- scratch ----------------
__device__ __align__(128) float g_queries[(size_t)NQ*DIM];
__device__ __align__(128) float g_q[(size_t)NQ*DIM];
__device__ __align__(128) __half g_kv_h[(size_t)NTOK*KVW];
__device__ __align__(128) float g_tmp[(size_t)NQ*DIM];

__device__ __align__(128) __half g_a_hi[(size_t)NTOK*DIM];
__device__ __align__(128) __half g_a_lo[(size_t)NTOK*DIM];
__device__ __align__(128) __half g_bkv[(size_t)KVW*DIM];
__device__ __align__(128) __half g_bq[(size_t)DIM*DIM];
__device__ __align__(128) __half g_bo[(size_t)DIM*DIM];
__device__ __align__(128) __half g_qn_hi[(size_t)NQ*DIM];
__device__ __align__(128) __half g_qn_lo[(size_t)NQ*DIM];
__device__ __align__(128) __half g_o_hi[(size_t)NQ*DIM];
__device__ __align__(128) __half g_o_lo[(size_t)NQ*DIM];

// ---------------- generic helpers ----------------
__device__ __forceinline__ uint32_t s2u(const void* p) {
    return (uint32_t)__cvta_generic_to_shared(p);
}
__device__ __forceinline__ void mbar_init(uint32_t a, uint32_t cnt) {
    asm volatile("mbarrier.init.shared.b64 [%0], %1;" :: "r"(a), "r"(cnt) : "memory");
}
__device__ __forceinline__ void mbar_wait(uint32_t a, uint32_t phase) {
    uint32_t done;
    do {
        asm volatile("{\n\t.reg .pred p;\n\t"
                     "mbarrier.try_wait.parity.shared::cta.b64 p, [%1], %2, 0x989680;\n\t"
                     "selp.b32 %0, 1, 0, p;\n\t}"
                     : "=r"(done) : "r"(a), "r"(phase) : "memory");
    } while (!done);
}
__device__ __forceinline__ void mbar_expect_tx(uint32_t a, uint32_t bytes) {
    asm volatile("mbarrier.arrive.expect_tx.shared.b64 _, [%0], %1;"
                 :: "r"(a), "r"(bytes) : "memory");
}
__device__ __forceinline__ void tma_load_2d(uint32_t dst, const void* map,
                                            int cx, int cy, uint32_t bar) {
    asm volatile("cp.async.bulk.tensor.2d.shared::cta.global.tile.mbarrier::complete_tx::bytes "
                 "[%0], [%1, {%2, %3}], [%4];"
                 :: "r"(dst), "l"(map), "r"(cx), "r"(cy), "r"(bar) : "memory");
}
// fp16 mma
__device__ __forceinline__ void mma16816h(float* c, const uint32_t* a, uint32_t b0, uint32_t b1) {
    asm volatile("mma.sync.aligned.m16n8k16.row.col.f32.f16.f16.f32 "
                 "{%0,%1,%2,%3}, {%4,%5,%6,%7}, {%8,%9}, {%0,%1,%2,%3};"
                 : "+f"(c[0]), "+f"(c[1]), "+f"(c[2]), "+f"(c[3])
                 : "r"(a[0]), "r"(a[1]), "r"(a[2]), "r"(a[3]), "r"(b0), "r"(b1));
}
// split float2 -> packed fp16x2 hi + lo
__device__ __forceinline__ void split2h(float2 v, uint32_t& hi, uint32_t& lo) {
    __half hx = __float2half_rn(v.x), hy = __float2half_rn(v.y);
    __half2 hp = __halves2half2(hx, hy);
    hi = *(uint32_t*)&hp;
    __half2 lp = __halves2half2(
        __float2half_rn(v.x - __half2float(hx)),
        __float2half_rn(v.y - __half2float(hy)));
    lo = *(uint32_t*)&lp;
}
// float2 -> packed fp16x2 (single)
__device__ __forceinline__ uint32_t pack2h(float2 v) {
    __half2 hp = __halves2half2(__float2half_rn(v.x), __float2half_rn(v.y));
    return *(uint32_t*)&hp;
}

#if TC_OK
// ---------------- tcgen05 helpers ----------------
__device__ __forceinline__ void tc_alloc(uint32_t smem_dst, uint32_t ncols) {
    asm volatile("tcgen05.alloc.cta_group::1.sync.aligned.shared::cta.b32 [%0], %1;"
                 :: "r"(smem_dst), "r"(ncols) : "memory");
}
__device__ __forceinline__ void tc_dealloc(uint32_t tmem, uint32_t ncols) {
    asm volatile("tcgen05.relinquish_alloc_permit.cta_group::1.sync.aligned;");
    asm volatile("tcgen05.dealloc.cta_group::1.sync.aligned.b32 %0, %1;" :: "r"(tmem), "r"(ncols));
}
__device__ __forceinline__ void tc_commit(uint32_t bar) {
    asm volatile("tcgen05.commit.cta_group::1.mbarrier::arrive::one.shared::cluster.b64 [%0];"
                 :: "r"(bar) : "memory");
}
__device__ __forceinline__ void tc_mma_f16_ss(uint32_t d, uint64_t ad, uint64_t bd,
                                              uint32_t idesc, uint32_t accum) {
    asm volatile("{\n\t.reg .pred p;\n\t"
                 "setp.ne.u32 p, %4, 0;\n\t"
                 "tcgen05.mma.cta_group::1.kind::f16 [%0], %1, %2, %3, {%5, %5, %5, %5}, p;\n\t}"
                 :: "r"(d), "l"(ad), "l"(bd), "r"(idesc), "r"(accum), "r"(0u) : "memory");
}
__device__ __forceinline__ void tc_fence_after() {
    asm volatile("tcgen05.fence::after_thread_sync;" ::: "memory");
}
#define LDTM_X32(r, addr) \
    asm volatile("tcgen05.ld.sync.aligned.32x32b.x32.b32 " \
        "{%0, %1, %2, %3, %4, %5, %6, %7, %8, %9, %10, %11, %12, %13, %14, %15, " \
        "%16, %17, %18, %19, %20, %21, %22, %23, %24, %25, %26, %27, %28, %29, %30, %31}, [%32];" \
        : "=r"((r)[0]), "=r"((r)[1]), "=r"((r)[2]), "=r"((r)[3]), \
          "=r"((r)[4]), "=r"((r)[5]), "=r"((r)[6]), "=r"((r)[7]), \
          "=r"((r)[8]), "=r"((r)[9]), "=r"((r)[10]), "=r"((r)[11]), \
          "=r"((r)[12]), "=r"((r)[13]), "=r"((r)[14]), "=r"((r)[15]), \
          "=r"((r)[16]), "=r"((r)[17]), "=r"((r)[18]), "=r"((r)[19]), \
          "=r"((r)[20]), "=r"((r)[21]), "=r"((r)[22]), "=r"((r)[23]), \
          "=r"((r)[24]), "=r"((r)[25]), "=r"((r)[26]), "=r"((r)[27]), \
          "=r"((r)[28]), "=r"((r)[29]), "=r"((r)[30]), "=r"((r)[31]) \
        : "r"(addr))
__device__ __forceinline__ void tc_wait_ld() {
    asm volatile("tcgen05.wait::ld.sync.aligned;" ::: "memory");
}
// SW64 K-major descriptor
static __device__ __forceinline__ uint64_t make_desc64(uint32_t addr) {
    const uint64_t base = (uint64_t(4) << 61) | (uint64_t(1) << 46) |
                          (uint64_t(32) << 32) | (uint64_t(1) << 16);
    return base | ((uint64_t)(addr >> 4) & 0x3FFFull);
}
#endif

// ---------------- weight transpose -> fp16 ----------------
__global__ void wsplit_kernel(const float* __restrict__ in,
                              __half* __restrict__ out,
                              int Kdim, int Ndim) {
    __shared__ float t[32][33];
    int n0 = blockIdx.x * 32, k0 = blockIdx.y * 32;
    int tx = threadIdx.x, ty = threadIdx.y;
    for (int r = ty; r < 32; r += 8)
        t[r][tx] = in[(size_t)(k0 + r) * Ndim + n0 + tx];
    __syncthreads();
    for (int r = ty; r < 32; r += 8)
        out[(size_t)(n0 + r) * Kdim + k0 + tx] = __float2half_rn(t[tx][r]);
}

// ---------------- fused: x split (fp16 hi/lo) + pooling + attention rmsnorm ----------------
__global__ void pool_rmsnorm_kernel(const float* __restrict__ x,
                                    const float* __restrict__ w) {
    int row = blockIdx.x;
    int tid = threadIdx.x;
    const float* base = x + (size_t)row * POOLN * DIM;
    float local = 0.f;
    #pragma unroll
    for (int i = 0; i < DIM / 512; i++) {
        int d = (tid + i * 256) * 2;
        float2 s = make_float2(0.f, 0.f);
        #pragma unroll
        for (int p = 0; p < POOLN; p++) {
            float2 v = *(const float2*)&base[(size_t)p*DIM + d];
            uint32_t hi, lo; split2h(v, hi, lo);
            size_t o = (size_t)(row * POOLN + p) * DIM + d;
            *(uint32_t*)&g_a_hi[o] = hi;
            *(uint32_t*)&g_a_lo[o] = lo;
            s.x += v.x; s.y += v.y;
        }
        s.x *= (1.0f / POOLN); s.y *= (1.0f / POOLN);
        *(float2*)&g_queries[(size_t)row*DIM + d] = s;
        local += s.x * s.x + s.y * s.y;
    }
    __shared__ float red[256];
    red[tid] = local; __syncthreads();
    for (int st = 128; st > 0; st >>= 1) {
        if (tid < st) red[tid] += red[tid + st];
        __syncthreads();
    }
    float rstd = rsqrtf(red[0] / DIM + EPS);
    #pragma unroll
    for (int i = 0; i < DIM / 512; i++) {
        int d = (tid + i * 256) * 2;
        float2 qv = *(float2*)&g_queries[(size_t)row*DIM + d];
        float2 wv = *(const float2*)&w[d];
        float2 v = make_float2(qv.x * rstd * wv.x, qv.y * rstd * wv.y);
        uint32_t hi, lo; split2h(v, hi, lo);
        *(uint32_t*)&g_qn_hi[(size_t)row*DIM + d] = hi;
        *(uint32_t*)&g_qn_lo[(size_t)row*DIM + d] = lo;
    }
}

// ---------------- fp16x2 GEMM: C[M,N] = (Ah+Al)[M,K] @ B[N,K]^T ----------------
#define BM 256
#define BN 256
#define GK 4096
#define KITERS (GK/32)
#define A_TILE_B 8192u
#define B_TILE_B 16384u
#define STAGE_BYTES (4u*A_TILE_B + B_TILE_B)   // 49152
#define NSTAGE 4
#define GEMM_SMEM (NSTAGE*STAGE_BYTES + 1024)

__global__ __launch_bounds__(256, 1)
void gemm3_kernel(int N, int nbm, int nbn, int half_out, int m_base,
                  const __grid_constant__ CUtensorMap mAh,
                  const __grid_constant__ CUtensorMap mAl,
                  const __grid_constant__ CUtensorMap mB,
                  const __half* __restrict__ Ah,
                  const __half* __restrict__ Al,
                  const __half* __restrict__ B,
                  float* __restrict__ C,
                  __half* __restrict__ Ch) {
    extern __shared__ char smraw[];
    char* smp = (char*)((((uintptr_t)smraw) + 1023) & ~(uintptr_t)1023);
    int tid = threadIdx.x;

    const int GM = 16;
    int bid = blockIdx.x;
    int group = bid / (GM * nbn);
    int first_m = group * GM;
    int gsz = min(nbm - first_m, GM);
    int pm = first_m + (bid % gsz);
    int pn = (bid % (GM * nbn)) / gsz;
    int m0 = m_base + pm * BM, n0 = pn * BN;

#if TC_OK
    uint32_t sb0 = s2u(smp);
    __shared__ __align__(8) unsigned long long full_b[NSTAGE], empty_b[NSTAGE], fin_b;
    __shared__ uint32_t tmem_ptr_sh;

    uint32_t full_a[NSTAGE], empty_a[NSTAGE], fin_a;
    #pragma unroll
    for (int i = 0; i < NSTAGE; i++) {
        full_a[i] = s2u(&full_b[i]);
        empty_a[i] = s2u(&empty_b[i]);
    }
    fin_a = s2u(&fin_b);

    if (tid < 32) tc_alloc(s2u(&tmem_ptr_sh), 512);
    if (tid == 0) {
        #pragma unroll
        for (int i = 0; i < NSTAGE; i++) {
            mbar_init(full_a[i], 1);
            mbar_init(empty_a[i], 1);
        }
        mbar_init(fin_a, 1);
    }
    __syncthreads();
    uint32_t tmem = tmem_ptr_sh;

    const uint32_t idesc = (1u<<4) | ((BN/8)<<17) | (8u<<24);

    if (tid == 32) {
        for (int it = 0; it < KITERS; it++) {
            int s = it % NSTAGE;
            uint32_t ph = ((it / NSTAGE) & 1) ^ 1u;
            mbar_wait(empty_a[s], ph);
            int k0 = it * 32;
            uint32_t sb = sb0 + s * STAGE_BYTES;
            uint32_t bar = full_a[s];
            mbar_expect_tx(bar, STAGE_BYTES);
            tma_load_2d(sb,                &mAh, k0, m0,       bar);
            tma_load_2d(sb + A_TILE_B,     &mAl, k0, m0,       bar);
            tma_load_2d(sb + 2u*A_TILE_B,  &mAh, k0, m0 + 128, bar);
            tma_load_2d(sb + 3u*A_TILE_B,  &mAl, k0, m0 + 128, bar);
            tma_load_2d(sb + 4u*A_TILE_B,  &mB,  k0, n0,       bar);
        }
    } else if (tid == 0) {
        for (int it = 0; it < KITERS; it++) {
            int s = it % NSTAGE;
            uint32_t ph = (it / NSTAGE) & 1;
            mbar_wait(full_a[s], ph);
            uint32_t sb = sb0 + s * STAGE_BYTES;
            uint64_t a0h = make_desc64(sb);
            uint64_t a0l = make_desc64(sb + A_TILE_B);
            uint64_t a1h = make_desc64(sb + 2u*A_TILE_B);
            uint64_t a1l = make_desc64(sb + 3u*A_TILE_B);
            uint64_t bd  = make_desc64(sb + 4u*A_TILE_B);
            #pragma unroll
            for (int ks = 0; ks < 2; ks++) {
                uint32_t acc = (it > 0 || ks > 0) ? 1u : 0u;
                uint64_t o = ks * 2;
                tc_mma_f16_ss(tmem,       a0h + o, bd + o, idesc, acc);
                tc_mma_f16_ss(tmem + 256, a1h + o, bd + o, idesc, acc);
                tc_mma_f16_ss(tmem,       a0l + o, bd + o, idesc, 1u);
                tc_mma_f16_ss(tmem + 256, a1l + o, bd + o, idesc, 1u);
            }
            tc_commit(empty_a[s]);
        }
        tc_commit(fin_a);
    }

    __syncthreads();
    mbar_wait(fin_a, 0);
    tc_fence_after();

    float* stg = (float*)smp;
    int w = tid >> 5, lane = tid & 31;
    #pragma unroll
    for (int half = 0; half < 2; half++) {
        if (w < 4) {
            for (int ch = 0; ch < 8; ch++) {
                uint32_t r[32];
                LDTM_X32(r, tmem + half * 256 + ch * 32);
                tc_wait_ld();
                #pragma unroll
                for (int j = 0; j < 32; j++)
                    stg[(size_t)(w * 32 + lane) * 260 + ch * 32 + j] = __uint_as_float(r[j]);
            }
        }
        __syncthreads();
        int c4 = (tid & 63) * 4;
        if (half_out) {
            for (int rr = tid >> 6; rr < 128; rr += 4) {
                float4 v = *(float4*)&stg[(size_t)rr * 260 + c4];
                uint32_t p0 = pack2h(make_float2(v.x, v.y));
                uint32_t p1 = pack2h(make_float2(v.z, v.w));
                *(uint2*)&Ch[(size_t)(m0 + half * 128 + rr) * N + n0 + c4] =
                    make_uint2(p0, p1);
            }
        } else {
            for (int rr = tid >> 6; rr < 128; rr += 4) {
                float4 v = *(float4*)&stg[(size_t)rr * 260 + c4];
                *(float4*)&C[(size_t)(m0 + half * 128 + rr) * N + n0 + c4] = v;
            }
        }
        __syncthreads();
    }
    if (tid < 32) tc_dealloc(tmem, 512);
#else
    // mma.sync fp16x2 fallback (bare sm_103; not selected on GB300)
    __half* sAh = (__half*)smp;
    __half* sAl = sAh + 128 * 40;
    __half* sB  = sAl + 128 * 40;

    int lane = tid & 31, w = tid >> 5;
    int wm = w & 3, wn = w >> 2;

    for (int mh = 0; mh < 2; mh++)
    for (int nh = 0; nh < 2; nh++) {
        int m0h = m0 + mh * 128;
        int n0h = n0 + nh * 128;
        float acc[2][4][4];
        #pragma unroll
        for (int mi = 0; mi < 2; mi++)
            #pragma unroll
            for (int ni = 0; ni < 4; ni++)
                #pragma unroll
                for (int j = 0; j < 4; j++) acc[mi][ni][j] = 0.f;

        for (int k0 = 0; k0 < GK; k0 += 32) {
            __syncthreads();
            for (int cid = tid; cid < 512; cid += 256) {
                int r = cid >> 2, c = cid & 3;
                *(uint4*)&sAh[r*40 + c*8] = *(const uint4*)&Ah[(size_t)(m0h+r)*GK + k0 + c*8];
                *(uint4*)&sAl[r*40 + c*8] = *(const uint4*)&Al[(size_t)(m0h+r)*GK + k0 + c*8];
                *(uint4*)&sB [r*40 + c*8] = *(const uint4*)&B [(size_t)(n0h+r)*GK + k0 + c*8];
            }
            __syncthreads();
            #pragma unroll
            for (int ks = 0; ks < 2; ks++) {
                int kc = (lane & 3) * 2 + ks * 16;
                uint32_t ah[2][4], al[2][4];
                #pragma unroll
                for (int mi = 0; mi < 2; mi++) {
                    int r = wm * 32 + mi * 16 + (lane >> 2);
                    ah[mi][0] = *(uint32_t*)&sAh[r*40 + kc];
                    ah[mi][1] = *(uint32_t*)&sAh[(r+8)*40 + kc];
                    ah[mi][2] = *(uint32_t*)&sAh[r*40 + kc + 8];
                    ah[mi][3] = *(uint32_t*)&sAh[(r+8)*40 + kc + 8];
                    al[mi][0] = *(uint32_t*)&sAl[r*40 + kc];
                    al[mi][1] = *(uint32_t*)&sAl[(r+8)*40 + kc];
                    al[mi][2] = *(uint32_t*)&sAl[r*40 + kc + 8];
                    al[mi][3] = *(uint32_t*)&sAl[(r+8)*40 + kc + 8];
                }
                #pragma unroll
                for (int ni = 0; ni < 4; ni++) {
                    int nr = wn * 64 + ni * 8 + (lane >> 2);
                    uint32_t b0 = *(uint32_t*)&sB[nr*40 + kc];
                    uint32_t b1 = *(uint32_t*)&sB[nr*40 + kc + 8];
                    #pragma unroll
                    for (int mi = 0; mi < 2; mi++) {
                        mma16816h(acc[mi][ni], ah[mi], b0, b1);
                        mma16816h(acc[mi][ni], al[mi], b0, b1);
                    }
                }
            }
        }
        #pragma unroll
        for (int mi = 0; mi < 2; mi++)
            #pragma unroll
            for (int ni = 0; ni < 4; ni++) {
                int r = m0h + wm * 32 + mi * 16 + (lane >> 2);
                int c = n0h + wn * 64 + ni * 8 + (lane & 3) * 2;
                if (half_out) {
                    *(uint32_t*)&Ch[(size_t)r * N + c] =
                        pack2h(make_float2(acc[mi][ni][0], acc[mi][ni][1]));
                    *(uint32_t*)&Ch[(size_t)(r+8) * N + c] =
                        pack2h(make_float2(acc[mi][ni][2], acc[mi][ni][3]));
                } else {
                    *(float2*)&C[(size_t)r * N + c] = make_float2(acc[mi][ni][0], acc[mi][ni][1]);
                    *(float2*)&C[(size_t)(r+8) * N + c] = make_float2(acc[mi][ni][2], acc[mi][ni][3]);
                }
            }
    }
#endif
}

// ---------------- tensor-core attention: 64-token chunks, seg_base param ----------------
#define SROW 514
#define QROW 132
#define VTROW 66
#define OFF_QH 65792
#define OFF_QL (OFF_QH + 8448)
#define OFF_K  (OFF_QL + 8448)
#define OFF_RI (OFF_K + 16896)
#define ATT2_SMEM (OFF_RI + 128)

__global__ __launch_bounds__(256, 2)
void attention2_kernel(int seg_base) {
    extern __shared__ char asmem[];
    float* sS = (float*)asmem;
    __half* sQh = (__half*)(asmem + OFF_QH);
    __half* sQl = (__half*)(asmem + OFF_QL);
    __half* sK  = (__half*)(asmem + OFF_K);
    float* rinv = (float*)(asmem + OFF_RI);

    int bid = blockIdx.x;
    int rt = bid & 1;
    int h  = (bid >> 1) & 31;
    int s  = seg_base + (bid >> 6);
    int q0 = s * RQ + rt * 32;
    int t0 = s * LSEG;

    int tid = threadIdx.x;
    int w = tid >> 5, lane = tid & 31;
    int wm = w & 1;
    int wn = w >> 1;
    int lr = lane >> 2, lc = lane & 3;

    // load Q (32 x 128) -> fp16 hi/lo smem
    for (int i = tid; i < 32 * 64; i += 256) {
        int r = i >> 6, c2 = (i & 63) * 2;
        float2 v = *(float2*)&g_q[(size_t)(q0 + r) * DIM + h * HDIM + c2];
        uint32_t hi, lo; split2h(v, hi, lo);
        *(uint32_t*)&sQh[r * QROW + c2] = hi;
        *(uint32_t*)&sQl[r * QROW + c2] = lo;
    }

    const float scale = rsqrtf((float)HDIM);

    // ---- phase 1: S = scale * Q K^T  (8 chunks of 64 tokens) ----
    for (int ck = 0; ck < 8; ck++) {
        __syncthreads();
        for (int i = tid; i < 64 * 32; i += 256) {
            int r = i >> 5, c4 = (i & 31) * 4;
            uint2 v = *(uint2*)&g_kv_h[(size_t)(t0 + ck * 64 + r) * KVW + h * HDIM + c4];
            *(uint2*)&sK[r * QROW + c4] = v;
        }
        __syncthreads();

        float acc[2][4];
        #pragma unroll
        for (int nt = 0; nt < 2; nt++)
            #pragma unroll
            for (int j = 0; j < 4; j++) acc[nt][j] = 0.f;
        int r0 = wm * 16 + lr;
        #pragma unroll
        for (int kk = 0; kk < 8; kk++) {
            int k0 = kk * 16;
            uint32_t ah[4], al[4];
            ah[0] = *(uint32_t*)&sQh[r0 * QROW + k0 + lc * 2];
            ah[1] = *(uint32_t*)&sQh[(r0 + 8) * QROW + k0 + lc * 2];
            ah[2] = *(uint32_t*)&sQh[r0 * QROW + k0 + 8 + lc * 2];
            ah[3] = *(uint32_t*)&sQh[(r0 + 8) * QROW + k0 + 8 + lc * 2];
            al[0] = *(uint32_t*)&sQl[r0 * QROW + k0 + lc * 2];
            al[1] = *(uint32_t*)&sQl[(r0 + 8) * QROW + k0 + lc * 2];
            al[2] = *(uint32_t*)&sQl[r0 * QROW + k0 + 8 + lc * 2];
            al[3] = *(uint32_t*)&sQl[(r0 + 8) * QROW + k0 + 8 + lc * 2];
            #pragma unroll
            for (int nt = 0; nt < 2; nt++) {
                int nb = wn * 16 + nt * 8;
                uint32_t b0 = *(uint32_t*)&sK[(nb + lr) * QROW + k0 + lc * 2];
                uint32_t b1 = *(uint32_t*)&sK[(nb + lr) * QROW + k0 + 8 + lc * 2];
                mma16816h(acc[nt], ah, b0, b1);
                mma16816h(acc[nt], al, b0, b1);
            }
        }
        #pragma unroll
        for (int nt = 0; nt < 2; nt++) {
            int col = ck * 64 + wn * 16 + nt * 8 + lc * 2;
            *(float2*)&sS[r0 * SROW + col] = make_float2(acc[nt][0] * scale, acc[nt][1] * scale);
            *(float2*)&sS[(r0 + 8) * SROW + col] = make_float2(acc[nt][2] * scale, acc[nt][3] * scale);
        }
    }
    __syncthreads();

    // ---- phase 2: softmax ----
    for (int j = 0; j < 4; j++) {
        int r = w * 4 + j;
        float m = -1e30f;
        for (int i = lane; i < LSEG; i += 32) m = fmaxf(m, sS[r * SROW + i]);
        #pragma unroll
        for (int o = 16; o; o >>= 1) m = fmaxf(m, __shfl_xor_sync(0xffffffffu, m, o));
        float sum = 0.f;
        for (int i = lane; i < LSEG; i += 32) {
            float e = __expf(sS[r * SROW + i] - m);
            sS[r * SROW + i] = e;
            sum += e;
        }
        #pragma unroll
        for (int o = 16; o; o >>= 1) sum += __shfl_xor_sync(0xffffffffu, sum, o);
        if (lane == 0) rinv[r] = 1.0f / sum;
    }

    // ---- phase 3: O = P V (8 chunks of 64 tokens) ----
    float oacc[4][4];
    #pragma unroll
    for (int nt = 0; nt < 4; nt++)
        #pragma unroll
        for (int j = 0; j < 4; j++) oacc[nt][j] = 0.f;

    for (int ck = 0; ck < 8; ck++) {
        __syncthreads();
        for (int i = tid; i < 64 * 64; i += 256) {
            int t = i >> 6, hd2 = (i & 63) * 2;
            uint32_t v = *(uint32_t*)&g_kv_h[(size_t)(t0 + ck * 64 + t) * KVW
                                             + NH * HDIM + h * HDIM + hd2];
            __half2 hv = *(__half2*)&v;
            sK[hd2 * VTROW + t] = __low2half(hv);
            sK[(hd2 + 1) * VTROW + t] = __high2half(hv);
        }
        __syncthreads();

        #pragma unroll
        for (int kk = 0; kk < 4; kk++) {
            int kt = ck * 64 + kk * 16;
            int kl = kk * 16;
            int r0 = wm * 16 + lr;
            float2 p0 = *(float2*)&sS[r0 * SROW + kt + lc * 2];
            float2 p1 = *(float2*)&sS[(r0 + 8) * SROW + kt + lc * 2];
            float2 p2 = *(float2*)&sS[r0 * SROW + kt + 8 + lc * 2];
            float2 p3 = *(float2*)&sS[(r0 + 8) * SROW + kt + 8 + lc * 2];
            uint32_t ah[4], al[4];
            split2h(p0, ah[0], al[0]);
            split2h(p1, ah[1], al[1]);
            split2h(p2, ah[2], al[2]);
            split2h(p3, ah[3], al[3]);
            #pragma unroll
            for (int nt = 0; nt < 4; nt++) {
                int hd0 = wn * 32 + nt * 8;
                uint32_t b0 = *(uint32_t*)&sK[(hd0 + lr) * VTROW + kl + lc * 2];
                uint32_t b1 = *(uint32_t*)&sK[(hd0 + lr) * VTROW + kl + 8 + lc * 2];
                mma16816h(oacc[nt], ah, b0, b1);
                mma16816h(oacc[nt], al, b0, b1);
            }
        }
    }

    // ---- writeback ----
    {
        int r0 = wm * 16 + lr;
        float ri0 = rinv[r0], ri1 = rinv[r0 + 8];
        #pragma unroll
        for (int nt = 0; nt < 4; nt++) {
            int c0 = h * HDIM + wn * 32 + nt * 8 + lc * 2;
            uint32_t hi, lo;
            split2h(make_float2(oacc[nt][0] * ri0, oacc[nt][1] * ri0), hi, lo);
            *(uint32_t*)&g_o_hi[(size_t)(q0 + r0) * DIM + c0] = hi;
            *(uint32_t*)&g_o_lo[(size_t)(q0 + r0) * DIM + c0] = lo;
            split2h(make_float2(oacc[nt][2] * ri1, oacc[nt][3] * ri1), hi, lo);
            *(uint32_t*)&g_o_hi[(size_t)(q0 + r0 + 8) * DIM + c0] = hi;
            *(uint32_t*)&g_o_lo[(size_t)(q0 + r0 + 8) * DIM + c0] = lo;
        }
    }
}

// ---------------- final: residual + rmsnorm ----------------
__global__ void final_kernel(const float* __restrict__ w, float* __restrict__ out) {
    int row = blockIdx.x;
    int tid = threadIdx.x;
    float vals[DIM / 256];
    float local = 0.f;
    #pragma unroll
    for (int i = 0; i < DIM / 256; i++) {
        int d = tid + i * 256;
        float v = g_tmp[(size_t)row * DIM + d] + g_queries[(size_t)row * DIM + d];
        vals[i] = v;
        local += v * v;
    }
    __shared__ float red[256];
    red[tid] = local; __syncthreads();
    for (int st = 128; st > 0; st >>= 1) {
        if (tid < st) red[tid] += red[tid + st];
        __syncthreads();
    }
    float rstd = rsqrtf(red[0] / DIM + EPS);
    #pragma unroll
    for (int i = 0; i < DIM / 256; i++) {
        int d = tid + i * 256;
        out[(size_t)row * DIM + d] = vals[i] * rstd * w[d];
    }
}

// ---------------- host: tensormap encode ----------------
typedef CUresult (*PFN_tmEncode)(CUtensorMap*, CUtensorMapDataType, cuuint32_t, void*,
                                 const cuuint64_t*, const cuuint64_t*, const cuuint32_t*,
                                 const cuuint32_t*, CUtensorMapInterleave, CUtensorMapSwizzle,
                                 CUtensorMapL2promotion, CUtensorMapFloatOOBfill);

static PFN_tmEncode get_encoder() {
    void* p = nullptr;
#if CUDART_VERSION >= 12050
    cudaDriverEntryPointQueryResult qr;
    cudaGetDriverEntryPointByVersion("cuTensorMapEncodeTiled", &p, 12000,
                                     cudaEnableDefault, &qr);
#else
    cudaGetDriverEntryPoint("cuTensorMapEncodeTiled", &p, cudaEnableDefault);
#endif
    return (PFN_tmEncode)p;
}

static void enc2d(PFN_tmEncode enc, CUtensorMap* m, void* base,
                  uint64_t rows, uint32_t boxRows) {
    cuuint64_t dims[2]    = {GK, rows};
    cuuint64_t strides[1] = {GK * 2};
    cuuint32_t box[2]     = {32, boxRows};
    cuuint32_t es[2]      = {1, 1};
    enc(m, CU_TENSOR_MAP_DATA_TYPE_FLOAT16, 2, base, dims, strides, box, es,
        CU_TENSOR_MAP_INTERLEAVE_NONE, CU_TENSOR_MAP_SWIZZLE_64B,
        CU_TENSOR_MAP_L2_PROMOTION_L2_128B, CU_TENSOR_MAP_FLOAT_OOB_FILL_NONE);
}

// ---------------- launch ----------------
extern "C" void kernel_launch(void* const* d_in, const int* in_sizes, int n_in,
                              void* d_out, int out_size) {
    const float* x      = (const float*)d_in[0];
    const float* attn_w = (const float*)d_in[1];
    const float* wq     = (const float*)d_in[2];
    const float* wkv    = (const float*)d_in[3];
    const float* wo     = (const float*)d_in[4];
    const float* out_w  = (const float*)d_in[5];
    float* out = (float*)d_out;

    float *pq, *ptmp;
    __half *pkvh, *pah, *pal, *pbkv, *pbq, *pbo, *pqnh, *pqnl, *poh, *pol;
    cudaGetSymbolAddress((void**)&pq,   g_q);
    cudaGetSymbolAddress((void**)&pkvh, g_kv_h);
    cudaGetSymbolAddress((void**)&ptmp, g_tmp);
    cudaGetSymbolAddress((void**)&pah,  g_a_hi);
    cudaGetSymbolAddress((void**)&pal,  g_a_lo);
    cudaGetSymbolAddress((void**)&pbkv, g_bkv);
    cudaGetSymbolAddress((void**)&pbq,  g_bq);
    cudaGetSymbolAddress((void**)&pbo,  g_bo);
    cudaGetSymbolAddress((void**)&pqnh, g_qn_hi);
    cudaGetSymbolAddress((void**)&pqnl, g_qn_lo);
    cudaGetSymbolAddress((void**)&poh,  g_o_hi);
    cudaGetSymbolAddress((void**)&pol,  g_o_lo);

    PFN_tmEncode enc = get_encoder();
    CUtensorMap mQA_h, mQA_l, mQB;
    CUtensorMap mKA_h, mKA_l, mKB;
    CUtensorMap mOA_h, mOA_l, mOB;
    enc2d(enc, &mQA_h, pqnh, NQ,   128);
    enc2d(enc, &mQA_l, pqnl, NQ,   128);
    enc2d(enc, &mQB,   pbq,  DIM,  256);
    enc2d(enc, &mKA_h, pah,  NTOK, 128);
    enc2d(enc, &mKA_l, pal,  NTOK, 128);
    enc2d(enc, &mKB,   pbkv, KVW,  256);
    enc2d(enc, &mOA_h, poh,  NQ,   128);
    enc2d(enc, &mOA_l, pol,  NQ,   128);
    enc2d(enc, &mOB,   pbo,  DIM,  256);

    cudaFuncSetAttribute(attention2_kernel,
                         cudaFuncAttributeMaxDynamicSharedMemorySize, (int)ATT2_SMEM);
    cudaFuncSetAttribute(gemm3_kernel,
                         cudaFuncAttributeMaxDynamicSharedMemorySize, (int)GEMM_SMEM);

    // side stream + events (created once; host objects only)
    static cudaStream_t s1 = nullptr;
    static cudaEvent_t evR = nullptr, evW = nullptr, evPool = nullptr;
    static cudaEvent_t evKV0 = nullptr, evKV1 = nullptr, evA0 = nullptr, evO0 = nullptr;
    if (s1 == nullptr) {
        cudaStreamCreateWithFlags(&s1, cudaStreamNonBlocking);
        cudaEventCreateWithFlags(&evR,    cudaEventDisableTiming);
        cudaEventCreateWithFlags(&evW,    cudaEventDisableTiming);
        cudaEventCreateWithFlags(&evPool, cudaEventDisableTiming);
        cudaEventCreateWithFlags(&evKV0,  cudaEventDisableTiming);
        cudaEventCreateWithFlags(&evKV1,  cudaEventDisableTiming);
        cudaEventCreateWithFlags(&evA0,   cudaEventDisableTiming);
        cudaEventCreateWithFlags(&evO0,   cudaEventDisableTiming);
    }

    // fork: weight transposes on s1, pooling on main
    cudaEventRecord(evR, 0);
    cudaStreamWaitEvent(s1, evR, 0);
    wsplit_kernel<<<dim3(KVW/32, DIM/32), dim3(32,8), 0, s1>>>(wkv, pbkv, DIM, KVW);
    wsplit_kernel<<<dim3(DIM/32, DIM/32), dim3(32,8), 0, s1>>>(wq, pbq, DIM, DIM);
    wsplit_kernel<<<dim3(DIM/32, DIM/32), dim3(32,8), 0, s1>>>(wo, pbo, DIM, DIM);
    cudaEventRecord(evW, s1);

    pool_rmsnorm_kernel<<<NQ, 256>>>(x, attn_w);
    cudaEventRecord(evPool, 0);

    // kv = x @ wkv on s1, two M-halves (fp16 output)
    cudaStreamWaitEvent(s1, evPool, 0);
    gemm3_kernel<<<(NTOK/2/BM)*(KVW/BN), 256, GEMM_SMEM, s1>>>(KVW, NTOK/2/BM, KVW/BN, 1, 0,
        mKA_h, mKA_l, mKB, pah, pal, pbkv, nullptr, pkvh);
    cudaEventRecord(evKV0, s1);
    gemm3_kernel<<<(NTOK/2/BM)*(KVW/BN), 256, GEMM_SMEM, s1>>>(KVW, NTOK/2/BM, KVW/BN, 1, NTOK/2,
        mKA_h, mKA_l, mKB, pah, pal, pbkv, nullptr, pkvh);
    cudaEventRecord(evKV1, s1);

    // q = qn @ wq on main (fp32 output)
    cudaStreamWaitEvent(0, evW, 0);
    gemm3_kernel<<<(NQ/BM)*(DIM/BN), 256, GEMM_SMEM>>>(DIM, NQ/BM, DIM/BN, 0, 0,
        mQA_h, mQA_l, mQB, pqnh, pqnl, pbq, pq, nullptr);

    // attention half 0 (segments 0-15) overlaps kv half 1
    cudaStreamWaitEvent(0, evKV0, 0);
    attention2_kernel<<<SEGN * NH, 256, ATT2_SMEM>>>(0);
    cudaEventRecord(evA0, 0);
    // attention half 1 (segments 16-31)
    cudaStreamWaitEvent(0, evKV1, 0);
    attention2_kernel<<<SEGN * NH, 256, ATT2_SMEM>>>(SEGN / 2);

    // o-GEMM half 0 (q rows 0..NQ/2, from attn half0) on s1 overlaps attn half1
    cudaStreamWaitEvent(s1, evA0, 0);
    gemm3_kernel<<<(NQ/2/BM)*(DIM/BN), 256, GEMM_SMEM, s1>>>(DIM, NQ/2/BM, DIM/BN, 0, 0,
        mOA_h, mOA_l, mOB, poh, pol, pbo, ptmp, nullptr);
    cudaEventRecord(evO0, s1);

    // o-GEMM half 1 on main (after attn half1, program order)
    gemm3_kernel<<<(NQ/2/BM)*(DIM/BN), 256, GEMM_SMEM>>>(DIM, NQ/2/BM, DIM/BN, 0, NQ/2,
        mOA_h, mOA_l, mOB, poh, pol, pbo, ptmp, nullptr);

    // final join
    cudaStreamWaitEvent(0, evO0, 0);
    final_kernel<<<NQ, 256>>>(out_w, out);
}

// round 16
// speedup vs baseline: 1.2303x; 1.2192x over previous
#include <cuda_runtime.h>
#include <cuda.h>
#include <cuda_bf16.h>
#include <cuda_fp16.h>
#include <math.h>
#include <stdint.h>

// ---------------- problem constants ----------------
#define SEGN   32
#define LSEG   512
#define RQ     64
#define POOLN  8
#define NH     32
#define HDIM   128
#define DIM    4096
#define NQ     (SEGN*RQ)     // 2048
#define NTOK   (SEGN*LSEG)   // 16384
#define KVW    (2*NH*HDIM)   // 8192
#define EPS    1e-5f

#if defined(__CUDA_ARCH_FEAT_SM103_ALL) || defined(__CUDA_ARCH_FEAT_SM100_ALL)
#define TC_OK 1
#else
#define TC_OK 0
#endif

// ---------------- scratch ----------------
__device__ __align__(128) float g_queries[(size_t)NQ*DIM];
__device__ __align__(128) float g_q[(size_t)NQ*DIM];
__device__ __align__(128) __half g_kv_h[(size_t)NTOK*KVW];
__device__ __align__(128) float g_tmp[(size_t)NQ*DIM];

__device__ __align__(128) __half g_a_hi[(size_t)NTOK*DIM];   // x in fp16 (single)
__device__ __align__(128) __half g_bkv[(size_t)KVW*DIM];
__device__ __align__(128) __half g_bq[(size_t)DIM*DIM];
__device__ __align__(128) __half g_bo[(size_t)DIM*DIM];
__device__ __align__(128) __half g_qn_hi[(size_t)NQ*DIM];
__device__ __align__(128) __half g_qn_lo[(size_t)NQ*DIM];
__device__ __align__(128) __half g_o_hi[(size_t)NQ*DIM];
__device__ __align__(128) __half g_o_lo[(size_t)NQ*DIM];

// ---------------- generic helpers ----------------
__device__ __forceinline__ uint32_t s2u(const void* p) {
    return (uint32_t)__cvta_generic_to_shared(p);
}
__device__ __forceinline__ void mbar_init(uint32_t a, uint32_t cnt) {
    asm volatile("mbarrier.init.shared.b64 [%0], %1;" :: "r"(a), "r"(cnt) : "memory");
}
__device__ __forceinline__ void mbar_wait(uint32_t a, uint32_t phase) {
    uint32_t done;
    do {
        asm volatile("{\n\t.reg .pred p;\n\t"
                     "mbarrier.try_wait.parity.shared::cta.b64 p, [%1], %2, 0x989680;\n\t"
                     "selp.b32 %0, 1, 0, p;\n\t}"
                     : "=r"(done) : "r"(a), "r"(phase) : "memory");
    } while (!done);
}
__device__ __forceinline__ void mbar_expect_tx(uint32_t a, uint32_t bytes) {
    asm volatile("mbarrier.arrive.expect_tx.shared.b64 _, [%0], %1;"
                 :: "r"(a), "r"(bytes) : "memory");
}
__device__ __forceinline__ void tma_load_2d(uint32_t dst, const void* map,
                                            int cx, int cy, uint32_t bar) {
    asm volatile("cp.async.bulk.tensor.2d.shared::cta.global.tile.mbarrier::complete_tx::bytes "
                 "[%0], [%1, {%2, %3}], [%4];"
                 :: "r"(dst), "l"(map), "r"(cx), "r"(cy), "r"(bar) : "memory");
}
// fp16 mma
__device__ __forceinline__ void mma16816h(float* c, const uint32_t* a, uint32_t b0, uint32_t b1) {
    asm volatile("mma.sync.aligned.m16n8k16.row.col.f32.f16.f16.f32 "
                 "{%0,%1,%2,%3}, {%4,%5,%6,%7}, {%8,%9}, {%0,%1,%2,%3};"
                 : "+f"(c[0]), "+f"(c[1]), "+f"(c[2]), "+f"(c[3])
                 : "r"(a[0]), "r"(a[1]), "r"(a[2]), "r"(a[3]), "r"(b0), "r"(b1));
}
// split float2 -> packed fp16x2 hi + lo
__device__ __forceinline__ void split2h(float2 v, uint32_t& hi, uint32_t& lo) {
    __half hx = __float2half_rn(v.x), hy = __float2half_rn(v.y);
    __half2 hp = __halves2half2(hx, hy);
    hi = *(uint32_t*)&hp;
    __half2 lp = __halves2half2(
        __float2half_rn(v.x - __half2float(hx)),
        __float2half_rn(v.y - __half2float(hy)));
    lo = *(uint32_t*)&lp;
}
// float2 -> packed fp16x2 (single)
__device__ __forceinline__ uint32_t pack2h(float2 v) {
    __half2 hp = __halves2half2(__float2half_rn(v.x), __float2half_rn(v.y));
    return *(uint32_t*)&hp;
}

#if TC_OK
// ---------------- tcgen05 helpers ----------------
__device__ __forceinline__ void tc_alloc(uint32_t smem_dst, uint32_t ncols) {
    asm volatile("tcgen05.alloc.cta_group::1.sync.aligned.shared::cta.b32 [%0], %1;"
                 :: "r"(smem_dst), "r"(ncols) : "memory");
}
__device__ __forceinline__ void tc_dealloc(uint32_t tmem, uint32_t ncols) {
    asm volatile("tcgen05.relinquish_alloc_permit.cta_group::1.sync.aligned;");
    asm volatile("tcgen05.dealloc.cta_group::1.sync.aligned.b32 %0, %1;" :: "r"(tmem), "r"(ncols));
}
__device__ __forceinline__ void tc_commit(uint32_t bar) {
    asm volatile("tcgen05.commit.cta_group::1.mbarrier::arrive::one.shared::cluster.b64 [%0];"
                 :: "r"(bar) : "memory");
}
__device__ __forceinline__ void tc_mma_f16_ss(uint32_t d, uint64_t ad, uint64_t bd,
                                              uint32_t idesc, uint32_t accum) {
    asm volatile("{\n\t.reg .pred p;\n\t"
                 "setp.ne.u32 p, %4, 0;\n\t"
                 "tcgen05.mma.cta_group::1.kind::f16 [%0], %1, %2, %3, {%5, %5, %5, %5}, p;\n\t}"
                 :: "r"(d), "l"(ad), "l"(bd), "r"(idesc), "r"(accum), "r"(0u) : "memory");
}
__device__ __forceinline__ void tc_fence_after() {
    asm volatile("tcgen05.fence::after_thread_sync;" ::: "memory");
}
#define LDTM_X32(r, addr) \
    asm volatile("tcgen05.ld.sync.aligned.32x32b.x32.b32 " \
        "{%0, %1, %2, %3, %4, %5, %6, %7, %8, %9, %10, %11, %12, %13, %14, %15, " \
        "%16, %17, %18, %19, %20, %21, %22, %23, %24, %25, %26, %27, %28, %29, %30, %31}, [%32];" \
        : "=r"((r)[0]), "=r"((r)[1]), "=r"((r)[2]), "=r"((r)[3]), \
          "=r"((r)[4]), "=r"((r)[5]), "=r"((r)[6]), "=r"((r)[7]), \
          "=r"((r)[8]), "=r"((r)[9]), "=r"((r)[10]), "=r"((r)[11]), \
          "=r"((r)[12]), "=r"((r)[13]), "=r"((r)[14]), "=r"((r)[15]), \
          "=r"((r)[16]), "=r"((r)[17]), "=r"((r)[18]), "=r"((r)[19]), \
          "=r"((r)[20]), "=r"((r)[21]), "=r"((r)[22]), "=r"((r)[23]), \
          "=r"((r)[24]), "=r"((r)[25]), "=r"((r)[26]), "=r"((r)[27]), \
          "=r"((r)[28]), "=r"((r)[29]), "=r"((r)[30]), "=r"((r)[31]) \
        : "r"(addr))
__device__ __forceinline__ void tc_wait_ld() {
    asm volatile("tcgen05.wait::ld.sync.aligned;" ::: "memory");
}
// SW64 K-major descriptor
static __device__ __forceinline__ uint64_t make_desc64(uint32_t addr) {
    const uint64_t base = (uint64_t(4) << 61) | (uint64_t(1) << 46) |
                          (uint64_t(32) << 32) | (uint64_t(1) << 16);
    return base | ((uint64_t)(addr >> 4) & 0x3FFFull);
}
#endif

// ---------------- weight transpose -> fp16 ----------------
__global__ void wsplit_kernel(const float* __restrict__ in,
                              __half* __restrict__ out,
                              int Kdim, int Ndim) {
    __shared__ float t[32][33];
    int n0 = blockIdx.x * 32, k0 = blockIdx.y * 32;
    int tx = threadIdx.x, ty = threadIdx.y;
    for (int r = ty; r < 32; r += 8)
        t[r][tx] = in[(size_t)(k0 + r) * Ndim + n0 + tx];
    __syncthreads();
    for (int r = ty; r < 32; r += 8)
        out[(size_t)(n0 + r) * Kdim + k0 + tx] = __float2half_rn(t[tx][r]);
}

// ---------------- fused: x -> fp16 single + pooling + attention rmsnorm ----------------
__global__ void pool_rmsnorm_kernel(const float* __restrict__ x,
                                    const float* __restrict__ w) {
    int row = blockIdx.x;
    int tid = threadIdx.x;
    const float* base = x + (size_t)row * POOLN * DIM;
    float local = 0.f;
    #pragma unroll
    for (int i = 0; i < DIM / 512; i++) {
        int d = (tid + i * 256) * 2;
        float2 s = make_float2(0.f, 0.f);
        #pragma unroll
        for (int p = 0; p < POOLN; p++) {
            float2 v = *(const float2*)&base[(size_t)p*DIM + d];
            size_t o = (size_t)(row * POOLN + p) * DIM + d;
            *(uint32_t*)&g_a_hi[o] = pack2h(v);
            s.x += v.x; s.y += v.y;
        }
        s.x *= (1.0f / POOLN); s.y *= (1.0f / POOLN);
        *(float2*)&g_queries[(size_t)row*DIM + d] = s;
        local += s.x * s.x + s.y * s.y;
    }
    __shared__ float red[256];
    red[tid] = local; __syncthreads();
    for (int st = 128; st > 0; st >>= 1) {
        if (tid < st) red[tid] += red[tid + st];
        __syncthreads();
    }
    float rstd = rsqrtf(red[0] / DIM + EPS);
    #pragma unroll
    for (int i = 0; i < DIM / 512; i++) {
        int d = (tid + i * 256) * 2;
        float2 qv = *(float2*)&g_queries[(size_t)row*DIM + d];
        float2 wv = *(const float2*)&w[d];
        float2 v = make_float2(qv.x * rstd * wv.x, qv.y * rstd * wv.y);
        uint32_t hi, lo; split2h(v, hi, lo);
        *(uint32_t*)&g_qn_hi[(size_t)row*DIM + d] = hi;
        *(uint32_t*)&g_qn_lo[(size_t)row*DIM + d] = lo;
    }
}

// ---------------- fp16 GEMM: C[M,N] = A[M,K] @ B[N,K]^T ----------------
// a_single=1: A is single fp16 (skip Al loads/MMAs).  half_out=1: fp16 output.
#define BM 256
#define BN 256
#define GK 4096
#define KITERS (GK/32)
#define A_TILE_B 8192u
#define B_TILE_B 16384u
#define STAGE_BYTES (4u*A_TILE_B + B_TILE_B)   // 49152 (layout fixed; lo slots unused if a_single)
#define NSTAGE 4
#define GEMM_SMEM (NSTAGE*STAGE_BYTES + 1024)

__global__ __launch_bounds__(256, 1)
void gemm3_kernel(int N, int nbm, int nbn, int half_out, int a_single, int m_base,
                  const __grid_constant__ CUtensorMap mAh,
                  const __grid_constant__ CUtensorMap mAl,
                  const __grid_constant__ CUtensorMap mB,
                  const __half* __restrict__ Ah,
                  const __half* __restrict__ Al,
                  const __half* __restrict__ B,
                  float* __restrict__ C,
                  __half* __restrict__ Ch) {
    extern __shared__ char smraw[];
    char* smp = (char*)((((uintptr_t)smraw) + 1023) & ~(uintptr_t)1023);
    int tid = threadIdx.x;

    const int GM = 16;
    int bid = blockIdx.x;
    int group = bid / (GM * nbn);
    int first_m = group * GM;
    int gsz = min(nbm - first_m, GM);
    int pm = first_m + (bid % gsz);
    int pn = (bid % (GM * nbn)) / gsz;
    int m0 = m_base + pm * BM, n0 = pn * BN;

#if TC_OK
    uint32_t sb0 = s2u(smp);
    __shared__ __align__(8) unsigned long long full_b[NSTAGE], empty_b[NSTAGE], fin_b;
    __shared__ uint32_t tmem_ptr_sh;

    uint32_t full_a[NSTAGE], empty_a[NSTAGE], fin_a;
    #pragma unroll
    for (int i = 0; i < NSTAGE; i++) {
        full_a[i] = s2u(&full_b[i]);
        empty_a[i] = s2u(&empty_b[i]);
    }
    fin_a = s2u(&fin_b);

    if (tid < 32) tc_alloc(s2u(&tmem_ptr_sh), 512);
    if (tid == 0) {
        #pragma unroll
        for (int i = 0; i < NSTAGE; i++) {
            mbar_init(full_a[i], 1);
            mbar_init(empty_a[i], 1);
        }
        mbar_init(fin_a, 1);
    }
    __syncthreads();
    uint32_t tmem = tmem_ptr_sh;

    const uint32_t idesc = (1u<<4) | ((BN/8)<<17) | (8u<<24);
    uint32_t tx_bytes = a_single ? (2u*A_TILE_B + B_TILE_B) : STAGE_BYTES;

    if (tid == 32) {
        for (int it = 0; it < KITERS; it++) {
            int s = it % NSTAGE;
            uint32_t ph = ((it / NSTAGE) & 1) ^ 1u;
            mbar_wait(empty_a[s], ph);
            int k0 = it * 32;
            uint32_t sb = sb0 + s * STAGE_BYTES;
            uint32_t bar = full_a[s];
            mbar_expect_tx(bar, tx_bytes);
            tma_load_2d(sb,                &mAh, k0, m0,       bar);
            tma_load_2d(sb + 2u*A_TILE_B,  &mAh, k0, m0 + 128, bar);
            if (!a_single) {
                tma_load_2d(sb + A_TILE_B,     &mAl, k0, m0,       bar);
                tma_load_2d(sb + 3u*A_TILE_B,  &mAl, k0, m0 + 128, bar);
            }
            tma_load_2d(sb + 4u*A_TILE_B,  &mB,  k0, n0,       bar);
        }
    } else if (tid == 0) {
        for (int it = 0; it < KITERS; it++) {
            int s = it % NSTAGE;
            uint32_t ph = (it / NSTAGE) & 1;
            mbar_wait(full_a[s], ph);
            uint32_t sb = sb0 + s * STAGE_BYTES;
            uint64_t a0h = make_desc64(sb);
            uint64_t a0l = make_desc64(sb + A_TILE_B);
            uint64_t a1h = make_desc64(sb + 2u*A_TILE_B);
            uint64_t a1l = make_desc64(sb + 3u*A_TILE_B);
            uint64_t bd  = make_desc64(sb + 4u*A_TILE_B);
            #pragma unroll
            for (int ks = 0; ks < 2; ks++) {
                uint32_t acc = (it > 0 || ks > 0) ? 1u : 0u;
                uint64_t o = ks * 2;
                tc_mma_f16_ss(tmem,       a0h + o, bd + o, idesc, acc);
                tc_mma_f16_ss(tmem + 256, a1h + o, bd + o, idesc, acc);
                if (!a_single) {
                    tc_mma_f16_ss(tmem,       a0l + o, bd + o, idesc, 1u);
                    tc_mma_f16_ss(tmem + 256, a1l + o, bd + o, idesc, 1u);
                }
            }
            tc_commit(empty_a[s]);
        }
        tc_commit(fin_a);
    }

    __syncthreads();
    mbar_wait(fin_a, 0);
    tc_fence_after();

    float* stg = (float*)smp;
    int w = tid >> 5, lane = tid & 31;
    #pragma unroll
    for (int half = 0; half < 2; half++) {
        if (w < 4) {
            for (int ch = 0; ch < 8; ch++) {
                uint32_t r[32];
                LDTM_X32(r, tmem + half * 256 + ch * 32);
                tc_wait_ld();
                #pragma unroll
                for (int j = 0; j < 32; j++)
                    stg[(size_t)(w * 32 + lane) * 260 + ch * 32 + j] = __uint_as_float(r[j]);
            }
        }
        __syncthreads();
        int c4 = (tid & 63) * 4;
        if (half_out) {
            for (int rr = tid >> 6; rr < 128; rr += 4) {
                float4 v = *(float4*)&stg[(size_t)rr * 260 + c4];
                uint32_t p0 = pack2h(make_float2(v.x, v.y));
                uint32_t p1 = pack2h(make_float2(v.z, v.w));
                *(uint2*)&Ch[(size_t)(m0 + half * 128 + rr) * N + n0 + c4] =
                    make_uint2(p0, p1);
            }
        } else {
            for (int rr = tid >> 6; rr < 128; rr += 4) {
                float4 v = *(float4*)&stg[(size_t)rr * 260 + c4];
                *(float4*)&C[(size_t)(m0 + half * 128 + rr) * N + n0 + c4] = v;
            }
        }
        __syncthreads();
    }
    if (tid < 32) tc_dealloc(tmem, 512);
#else
    // mma.sync fallback (bare sm_103; not selected on GB300)
    __half* sAh = (__half*)smp;
    __half* sAl = sAh + 128 * 40;
    __half* sB  = sAl + 128 * 40;

    int lane = tid & 31, w = tid >> 5;
    int wm = w & 3, wn = w >> 2;

    for (int mh = 0; mh < 2; mh++)
    for (int nh = 0; nh < 2; nh++) {
        int m0h = m0 + mh * 128;
        int n0h = n0 + nh * 128;
        float acc[2][4][4];
        #pragma unroll
        for (int mi = 0; mi < 2; mi++)
            #pragma unroll
            for (int ni = 0; ni < 4; ni++)
                #pragma unroll
                for (int j = 0; j < 4; j++) acc[mi][ni][j] = 0.f;

        for (int k0 = 0; k0 < GK; k0 += 32) {
            __syncthreads();
            for (int cid = tid; cid < 512; cid += 256) {
                int r = cid >> 2, c = cid & 3;
                *(uint4*)&sAh[r*40 + c*8] = *(const uint4*)&Ah[(size_t)(m0h+r)*GK + k0 + c*8];
                if (!a_single)
                    *(uint4*)&sAl[r*40 + c*8] = *(const uint4*)&Al[(size_t)(m0h+r)*GK + k0 + c*8];
                *(uint4*)&sB [r*40 + c*8] = *(const uint4*)&B [(size_t)(n0h+r)*GK + k0 + c*8];
            }
            __syncthreads();
            #pragma unroll
            for (int ks = 0; ks < 2; ks++) {
                int kc = (lane & 3) * 2 + ks * 16;
                uint32_t ah[2][4], al[2][4];
                #pragma unroll
                for (int mi = 0; mi < 2; mi++) {
                    int r = wm * 32 + mi * 16 + (lane >> 2);
                    ah[mi][0] = *(uint32_t*)&sAh[r*40 + kc];
                    ah[mi][1] = *(uint32_t*)&sAh[(r+8)*40 + kc];
                    ah[mi][2] = *(uint32_t*)&sAh[r*40 + kc + 8];
                    ah[mi][3] = *(uint32_t*)&sAh[(r+8)*40 + kc + 8];
                    if (!a_single) {
                        al[mi][0] = *(uint32_t*)&sAl[r*40 + kc];
                        al[mi][1] = *(uint32_t*)&sAl[(r+8)*40 + kc];
                        al[mi][2] = *(uint32_t*)&sAl[r*40 + kc + 8];
                        al[mi][3] = *(uint32_t*)&sAl[(r+8)*40 + kc + 8];
                    }
                }
                #pragma unroll
                for (int ni = 0; ni < 4; ni++) {
                    int nr = wn * 64 + ni * 8 + (lane >> 2);
                    uint32_t b0 = *(uint32_t*)&sB[nr*40 + kc];
                    uint32_t b1 = *(uint32_t*)&sB[nr*40 + kc + 8];
                    #pragma unroll
                    for (int mi = 0; mi < 2; mi++) {
                        mma16816h(acc[mi][ni], ah[mi], b0, b1);
                        if (!a_single) mma16816h(acc[mi][ni], al[mi], b0, b1);
                    }
                }
            }
        }
        #pragma unroll
        for (int mi = 0; mi < 2; mi++)
            #pragma unroll
            for (int ni = 0; ni < 4; ni++) {
                int r = m0h + wm * 32 + mi * 16 + (lane >> 2);
                int c = n0h + wn * 64 + ni * 8 + (lane & 3) * 2;
                if (half_out) {
                    *(uint32_t*)&Ch[(size_t)r * N + c] =
                        pack2h(make_float2(acc[mi][ni][0], acc[mi][ni][1]));
                    *(uint32_t*)&Ch[(size_t)(r+8) * N + c] =
                        pack2h(make_float2(acc[mi][ni][2], acc[mi][ni][3]));
                } else {
                    *(float2*)&C[(size_t)r * N + c] = make_float2(acc[mi][ni][0], acc[mi][ni][1]);
                    *(float2*)&C[(size_t)(r+8) * N + c] = make_float2(acc[mi][ni][2], acc[mi][ni][3]);
                }
            }
    }
#endif
}

// ---------------- tensor-core attention: 64-token chunks, seg_base param ----------------
#define SROW 514
#define QROW 132
#define VTROW 66
#define OFF_QH 65792
#define OFF_QL (OFF_QH + 8448)
#define OFF_K  (OFF_QL + 8448)
#define OFF_RI (OFF_K + 16896)
#define ATT2_SMEM (OFF_RI + 128)

__global__ __launch_bounds__(256, 2)
void attention2_kernel(int seg_base) {
    extern __shared__ char asmem[];
    float* sS = (float*)asmem;
    __half* sQh = (__half*)(asmem + OFF_QH);
    __half* sQl = (__half*)(asmem + OFF_QL);
    __half* sK  = (__half*)(asmem + OFF_K);
    float* rinv = (float*)(asmem + OFF_RI);

    int bid = blockIdx.x;
    int rt = bid & 1;
    int h  = (bid >> 1) & 31;
    int s  = seg_base + (bid >> 6);
    int q0 = s * RQ + rt * 32;
    int t0 = s * LSEG;

    int tid = threadIdx.x;
    int w = tid >> 5, lane = tid & 31;
    int wm = w & 1;
    int wn = w >> 1;
    int lr = lane >> 2, lc = lane & 3;

    // load Q (32 x 128) -> fp16 hi/lo smem
    for (int i = tid; i < 32 * 64; i += 256) {
        int r = i >> 6, c2 = (i & 63) * 2;
        float2 v = *(float2*)&g_q[(size_t)(q0 + r) * DIM + h * HDIM + c2];
        uint32_t hi, lo; split2h(v, hi, lo);
        *(uint32_t*)&sQh[r * QROW + c2] = hi;
        *(uint32_t*)&sQl[r * QROW + c2] = lo;
    }

    const float scale = rsqrtf((float)HDIM);

    // ---- phase 1: S = scale * Q K^T  (8 chunks of 64 tokens) ----
    for (int ck = 0; ck < 8; ck++) {
        __syncthreads();
        for (int i = tid; i < 64 * 32; i += 256) {
            int r = i >> 5, c4 = (i & 31) * 4;
            uint2 v = *(uint2*)&g_kv_h[(size_t)(t0 + ck * 64 + r) * KVW + h * HDIM + c4];
            *(uint2*)&sK[r * QROW + c4] = v;
        }
        __syncthreads();

        float acc[2][4];
        #pragma unroll
        for (int nt = 0; nt < 2; nt++)
            #pragma unroll
            for (int j = 0; j < 4; j++) acc[nt][j] = 0.f;
        int r0 = wm * 16 + lr;
        #pragma unroll
        for (int kk = 0; kk < 8; kk++) {
            int k0 = kk * 16;
            uint32_t ah[4], al[4];
            ah[0] = *(uint32_t*)&sQh[r0 * QROW + k0 + lc * 2];
            ah[1] = *(uint32_t*)&sQh[(r0 + 8) * QROW + k0 + lc * 2];
            ah[2] = *(uint32_t*)&sQh[r0 * QROW + k0 + 8 + lc * 2];
            ah[3] = *(uint32_t*)&sQh[(r0 + 8) * QROW + k0 + 8 + lc * 2];
            al[0] = *(uint32_t*)&sQl[r0 * QROW + k0 + lc * 2];
            al[1] = *(uint32_t*)&sQl[(r0 + 8) * QROW + k0 + lc * 2];
            al[2] = *(uint32_t*)&sQl[r0 * QROW + k0 + 8 + lc * 2];
            al[3] = *(uint32_t*)&sQl[(r0 + 8) * QROW + k0 + 8 + lc * 2];
            #pragma unroll
            for (int nt = 0; nt < 2; nt++) {
                int nb = wn * 16 + nt * 8;
                uint32_t b0 = *(uint32_t*)&sK[(nb + lr) * QROW + k0 + lc * 2];
                uint32_t b1 = *(uint32_t*)&sK[(nb + lr) * QROW + k0 + 8 + lc * 2];
                mma16816h(acc[nt], ah, b0, b1);
                mma16816h(acc[nt], al, b0, b1);
            }
        }
        #pragma unroll
        for (int nt = 0; nt < 2; nt++) {
            int col = ck * 64 + wn * 16 + nt * 8 + lc * 2;
            *(float2*)&sS[r0 * SROW + col] = make_float2(acc[nt][0] * scale, acc[nt][1] * scale);
            *(float2*)&sS[(r0 + 8) * SROW + col] = make_float2(acc[nt][2] * scale, acc[nt][3] * scale);
        }
    }
    __syncthreads();

    // ---- phase 2: softmax ----
    for (int j = 0; j < 4; j++) {
        int r = w * 4 + j;
        float m = -1e30f;
        for (int i = lane; i < LSEG; i += 32) m = fmaxf(m, sS[r * SROW + i]);
        #pragma unroll
        for (int o = 16; o; o >>= 1) m = fmaxf(m, __shfl_xor_sync(0xffffffffu, m, o));
        float sum = 0.f;
        for (int i = lane; i < LSEG; i += 32) {
            float e = __expf(sS[r * SROW + i] - m);
            sS[r * SROW + i] = e;
            sum += e;
        }
        #pragma unroll
        for (int o = 16; o; o >>= 1) sum += __shfl_xor_sync(0xffffffffu, sum, o);
        if (lane == 0) rinv[r] = 1.0f / sum;
    }

    // ---- phase 3: O = P V (8 chunks of 64 tokens) ----
    float oacc[4][4];
    #pragma unroll
    for (int nt = 0; nt < 4; nt++)
        #pragma unroll
        for (int j = 0; j < 4; j++) oacc[nt][j] = 0.f;

    for (int ck = 0; ck < 8; ck++) {
        __syncthreads();
        for (int i = tid; i < 64 * 64; i += 256) {
            int t = i >> 6, hd2 = (i & 63) * 2;
            uint32_t v = *(uint32_t*)&g_kv_h[(size_t)(t0 + ck * 64 + t) * KVW
                                             + NH * HDIM + h * HDIM + hd2];
            __half2 hv = *(__half2*)&v;
            sK[hd2 * VTROW + t] = __low2half(hv);
            sK[(hd2 + 1) * VTROW + t] = __high2half(hv);
        }
        __syncthreads();

        #pragma unroll
        for (int kk = 0; kk < 4; kk++) {
            int kt = ck * 64 + kk * 16;
            int kl = kk * 16;
            int r0 = wm * 16 + lr;
            float2 p0 = *(float2*)&sS[r0 * SROW + kt + lc * 2];
            float2 p1 = *(float2*)&sS[(r0 + 8) * SROW + kt + lc * 2];
            float2 p2 = *(float2*)&sS[r0 * SROW + kt + 8 + lc * 2];
            float2 p3 = *(float2*)&sS[(r0 + 8) * SROW + kt + 8 + lc * 2];
            uint32_t ah[4], al[4];
            split2h(p0, ah[0], al[0]);
            split2h(p1, ah[1], al[1]);
            split2h(p2, ah[2], al[2]);
            split2h(p3, ah[3], al[3]);
            #pragma unroll
            for (int nt = 0; nt < 4; nt++) {
                int hd0 = wn * 32 + nt * 8;
                uint32_t b0 = *(uint32_t*)&sK[(hd0 + lr) * VTROW + kl + lc * 2];
                uint32_t b1 = *(uint32_t*)&sK[(hd0 + lr) * VTROW + kl + 8 + lc * 2];
                mma16816h(oacc[nt], ah, b0, b1);
                mma16816h(oacc[nt], al, b0, b1);
            }
        }
    }

    // ---- writeback ----
    {
        int r0 = wm * 16 + lr;
        float ri0 = rinv[r0], ri1 = rinv[r0 + 8];
        #pragma unroll
        for (int nt = 0; nt < 4; nt++) {
            int c0 = h * HDIM + wn * 32 + nt * 8 + lc * 2;
            uint32_t hi, lo;
            split2h(make_float2(oacc[nt][0] * ri0, oacc[nt][1] * ri0), hi, lo);
            *(uint32_t*)&g_o_hi[(size_t)(q0 + r0) * DIM + c0] = hi;
            *(uint32_t*)&g_o_lo[(size_t)(q0 + r0) * DIM + c0] = lo;
            split2h(make_float2(oacc[nt][2] * ri1, oacc[nt][3] * ri1), hi, lo);
            *(uint32_t*)&g_o_hi[(size_t)(q0 + r0 + 8) * DIM + c0] = hi;
            *(uint32_t*)&g_o_lo[(size_t)(q0 + r0 + 8) * DIM + c0] = lo;
        }
    }
}

// ---------------- final: residual + rmsnorm ----------------
__global__ void final_kernel(const float* __restrict__ w, float* __restrict__ out) {
    int row = blockIdx.x;
    int tid = threadIdx.x;
    float vals[DIM / 256];
    float local = 0.f;
    #pragma unroll
    for (int i = 0; i < DIM / 256; i++) {
        int d = tid + i * 256;
        float v = g_tmp[(size_t)row * DIM + d] + g_queries[(size_t)row * DIM + d];
        vals[i] = v;
        local += v * v;
    }
    __shared__ float red[256];
    red[tid] = local; __syncthreads();
    for (int st = 128; st > 0; st >>= 1) {
        if (tid < st) red[tid] += red[tid + st];
        __syncthreads();
    }
    float rstd = rsqrtf(red[0] / DIM + EPS);
    #pragma unroll
    for (int i = 0; i < DIM / 256; i++) {
        int d = tid + i * 256;
        out[(size_t)row * DIM + d] = vals[i] * rstd * w[d];
    }
}

// ---------------- host: tensormap encode ----------------
typedef CUresult (*PFN_tmEncode)(CUtensorMap*, CUtensorMapDataType, cuuint32_t, void*,
                                 const cuuint64_t*, const cuuint64_t*, const cuuint32_t*,
                                 const cuuint32_t*, CUtensorMapInterleave, CUtensorMapSwizzle,
                                 CUtensorMapL2promotion, CUtensorMapFloatOOBfill);

static PFN_tmEncode get_encoder() {
    void* p = nullptr;
#if CUDART_VERSION >= 12050
    cudaDriverEntryPointQueryResult qr;
    cudaGetDriverEntryPointByVersion("cuTensorMapEncodeTiled", &p, 12000,
                                     cudaEnableDefault, &qr);
#else
    cudaGetDriverEntryPoint("cuTensorMapEncodeTiled", &p, cudaEnableDefault);
#endif
    return (PFN_tmEncode)p;
}

static void enc2d(PFN_tmEncode enc, CUtensorMap* m, void* base,
                  uint64_t rows, uint32_t boxRows) {
    cuuint64_t dims[2]    = {GK, rows};
    cuuint64_t strides[1] = {GK * 2};
    cuuint32_t box[2]     = {32, boxRows};
    cuuint32_t es[2]      = {1, 1};
    enc(m, CU_TENSOR_MAP_DATA_TYPE_FLOAT16, 2, base, dims, strides, box, es,
        CU_TENSOR_MAP_INTERLEAVE_NONE, CU_TENSOR_MAP_SWIZZLE_64B,
        CU_TENSOR_MAP_L2_PROMOTION_L2_128B, CU_TENSOR_MAP_FLOAT_OOB_FILL_NONE);
}

// ---------------- launch ----------------
extern "C" void kernel_launch(void* const* d_in, const int* in_sizes, int n_in,
                              void* d_out, int out_size) {
    const float* x      = (const float*)d_in[0];
    const float* attn_w = (const float*)d_in[1];
    const float* wq     = (const float*)d_in[2];
    const float* wkv    = (const float*)d_in[3];
    const float* wo     = (const float*)d_in[4];
    const float* out_w  = (const float*)d_in[5];
    float* out = (float*)d_out;

    float *pq, *ptmp;
    __half *pkvh, *pah, *pbkv, *pbq, *pbo, *pqnh, *pqnl, *poh, *pol;
    cudaGetSymbolAddress((void**)&pq,   g_q);
    cudaGetSymbolAddress((void**)&pkvh, g_kv_h);
    cudaGetSymbolAddress((void**)&ptmp, g_tmp);
    cudaGetSymbolAddress((void**)&pah,  g_a_hi);
    cudaGetSymbolAddress((void**)&pbkv, g_bkv);
    cudaGetSymbolAddress((void**)&pbq,  g_bq);
    cudaGetSymbolAddress((void**)&pbo,  g_bo);
    cudaGetSymbolAddress((void**)&pqnh, g_qn_hi);
    cudaGetSymbolAddress((void**)&pqnl, g_qn_lo);
    cudaGetSymbolAddress((void**)&poh,  g_o_hi);
    cudaGetSymbolAddress((void**)&pol,  g_o_lo);

    PFN_tmEncode enc = get_encoder();
    CUtensorMap mQA_h, mQA_l, mQB;
    CUtensorMap mKA_h, mKB;
    CUtensorMap mOA_h, mOA_l, mOB;
    enc2d(enc, &mQA_h, pqnh, NQ,   128);
    enc2d(enc, &mQA_l, pqnl, NQ,   128);
    enc2d(enc, &mQB,   pbq,  DIM,  256);
    enc2d(enc, &mKA_h, pah,  NTOK, 128);
    enc2d(enc, &mKB,   pbkv, KVW,  256);
    enc2d(enc, &mOA_h, poh,  NQ,   128);
    enc2d(enc, &mOA_l, pol,  NQ,   128);
    enc2d(enc, &mOB,   pbo,  DIM,  256);

    cudaFuncSetAttribute(attention2_kernel,
                         cudaFuncAttributeMaxDynamicSharedMemorySize, (int)ATT2_SMEM);
    cudaFuncSetAttribute(gemm3_kernel,
                         cudaFuncAttributeMaxDynamicSharedMemorySize, (int)GEMM_SMEM);

    // side stream + events (created once; host objects only)
    static cudaStream_t s1 = nullptr;
    static cudaEvent_t evR = nullptr, evW = nullptr, evPool = nullptr;
    static cudaEvent_t evKV0 = nullptr, evKV1 = nullptr;
    if (s1 == nullptr) {
        cudaStreamCreateWithFlags(&s1, cudaStreamNonBlocking);
        cudaEventCreateWithFlags(&evR,    cudaEventDisableTiming);
        cudaEventCreateWithFlags(&evW,    cudaEventDisableTiming);
        cudaEventCreateWithFlags(&evPool, cudaEventDisableTiming);
        cudaEventCreateWithFlags(&evKV0,  cudaEventDisableTiming);
        cudaEventCreateWithFlags(&evKV1,  cudaEventDisableTiming);
    }

    // fork: weight transposes on s1, pooling on main
    cudaEventRecord(evR, 0);
    cudaStreamWaitEvent(s1, evR, 0);
    wsplit_kernel<<<dim3(KVW/32, DIM/32), dim3(32,8), 0, s1>>>(wkv, pbkv, DIM, KVW);
    wsplit_kernel<<<dim3(DIM/32, DIM/32), dim3(32,8), 0, s1>>>(wq, pbq, DIM, DIM);
    wsplit_kernel<<<dim3(DIM/32, DIM/32), dim3(32,8), 0, s1>>>(wo, pbo, DIM, DIM);
    cudaEventRecord(evW, s1);

    pool_rmsnorm_kernel<<<NQ, 256>>>(x, attn_w);
    cudaEventRecord(evPool, 0);

    // kv = x @ wkv on s1, two M-halves (fp16 output, single-fp16 A)
    cudaStreamWaitEvent(s1, evPool, 0);
    gemm3_kernel<<<(NTOK/2/BM)*(KVW/BN), 256, GEMM_SMEM, s1>>>(KVW, NTOK/2/BM, KVW/BN, 1, 1, 0,
        mKA_h, mKA_h, mKB, pah, pah, pbkv, nullptr, pkvh);
    cudaEventRecord(evKV0, s1);
    gemm3_kernel<<<(NTOK/2/BM)*(KVW/BN), 256, GEMM_SMEM, s1>>>(KVW, NTOK/2/BM, KVW/BN, 1, 1, NTOK/2,
        mKA_h, mKA_h, mKB, pah, pah, pbkv, nullptr, pkvh);
    cudaEventRecord(evKV1, s1);

    // q = qn @ wq on main (fp32 output, hi/lo A)
    cudaStreamWaitEvent(0, evW, 0);
    gemm3_kernel<<<(NQ/BM)*(DIM/BN), 256, GEMM_SMEM>>>(DIM, NQ/BM, DIM/BN, 0, 0, 0,
        mQA_h, mQA_l, mQB, pqnh, pqnl, pbq, pq, nullptr);

    // attention half 0 (segments 0-15) overlaps kv half 1
    cudaStreamWaitEvent(0, evKV0, 0);
    attention2_kernel<<<SEGN * NH, 256, ATT2_SMEM>>>(0);
    // attention half 1 (segments 16-31)
    cudaStreamWaitEvent(0, evKV1, 0);
    attention2_kernel<<<SEGN * NH, 256, ATT2_SMEM>>>(SEGN / 2);

    // tmp = o @ wo (fp32 output, hi/lo A)
    gemm3_kernel<<<(NQ/BM)*(DIM/BN), 256, GEMM_SMEM>>>(DIM, NQ/BM, DIM/BN, 0, 0, 0,
        mOA_h, mOA_l, mOB, poh, pol, pbo, ptmp, nullptr);
    // residual + rmsnorm
    final_kernel<<<NQ, 256>>>(out_w, out);
}

// round 17
// speedup vs baseline: 1.2994x; 1.0562x over previous
#include <cuda_runtime.h>
#include <cuda.h>
#include <cuda_bf16.h>
#include <cuda_fp16.h>
#include <math.h>
#include <stdint.h>

// ---------------- problem constants ----------------
#define SEGN   32
#define LSEG   512
#define RQ     64
#define POOLN  8
#define NH     32
#define HDIM   128
#define DIM    4096
#define NQ     (SEGN*RQ)     // 2048
#define NTOK   (SEGN*LSEG)   // 16384
#define KVW    (2*NH*HDIM)   // 8192
#define EPS    1e-5f

#if defined(__CUDA_ARCH_FEAT_SM103_ALL) || defined(__CUDA_ARCH_FEAT_SM100_ALL)
#define TC_OK 1
#else
#define TC_OK 0
#endif

// ---------------- scratch ----------------
__device__ __align__(128) float g_queries[(size_t)NQ*DIM];
__device__ __align__(128) __half g_q_h[(size_t)NQ*DIM];      // q projection (fp16)
__device__ __align__(128) __half g_kv_h[(size_t)NTOK*KVW];
__device__ __align__(128) float g_tmp[(size_t)NQ*DIM];

__device__ __align__(128) __half g_a_hi[(size_t)NTOK*DIM];   // x in fp16 (single)
__device__ __align__(128) __half g_bkv[(size_t)KVW*DIM];
__device__ __align__(128) __half g_bq[(size_t)DIM*DIM];
__device__ __align__(128) __half g_bo[(size_t)DIM*DIM];
__device__ __align__(128) __half g_qn_h[(size_t)NQ*DIM];     // qn (fp16 single)
__device__ __align__(128) __half g_o_h[(size_t)NQ*DIM];      // attention out (fp16 single)

// ---------------- generic helpers ----------------
__device__ __forceinline__ uint32_t s2u(const void* p) {
    return (uint32_t)__cvta_generic_to_shared(p);
}
__device__ __forceinline__ void mbar_init(uint32_t a, uint32_t cnt) {
    asm volatile("mbarrier.init.shared.b64 [%0], %1;" :: "r"(a), "r"(cnt) : "memory");
}
__device__ __forceinline__ void mbar_wait(uint32_t a, uint32_t phase) {
    uint32_t done;
    do {
        asm volatile("{\n\t.reg .pred p;\n\t"
                     "mbarrier.try_wait.parity.shared::cta.b64 p, [%1], %2, 0x989680;\n\t"
                     "selp.b32 %0, 1, 0, p;\n\t}"
                     : "=r"(done) : "r"(a), "r"(phase) : "memory");
    } while (!done);
}
__device__ __forceinline__ void mbar_expect_tx(uint32_t a, uint32_t bytes) {
    asm volatile("mbarrier.arrive.expect_tx.shared.b64 _, [%0], %1;"
                 :: "r"(a), "r"(bytes) : "memory");
}
__device__ __forceinline__ void tma_load_2d(uint32_t dst, const void* map,
                                            int cx, int cy, uint32_t bar) {
    asm volatile("cp.async.bulk.tensor.2d.shared::cta.global.tile.mbarrier::complete_tx::bytes "
                 "[%0], [%1, {%2, %3}], [%4];"
                 :: "r"(dst), "l"(map), "r"(cx), "r"(cy), "r"(bar) : "memory");
}
// fp16 mma
__device__ __forceinline__ void mma16816h(float* c, const uint32_t* a, uint32_t b0, uint32_t b1) {
    asm volatile("mma.sync.aligned.m16n8k16.row.col.f32.f16.f16.f32 "
                 "{%0,%1,%2,%3}, {%4,%5,%6,%7}, {%8,%9}, {%0,%1,%2,%3};"
                 : "+f"(c[0]), "+f"(c[1]), "+f"(c[2]), "+f"(c[3])
                 : "r"(a[0]), "r"(a[1]), "r"(a[2]), "r"(a[3]), "r"(b0), "r"(b1));
}
// split float2 -> packed fp16x2 hi + lo
__device__ __forceinline__ void split2h(float2 v, uint32_t& hi, uint32_t& lo) {
    __half hx = __float2half_rn(v.x), hy = __float2half_rn(v.y);
    __half2 hp = __halves2half2(hx, hy);
    hi = *(uint32_t*)&hp;
    __half2 lp = __halves2half2(
        __float2half_rn(v.x - __half2float(hx)),
        __float2half_rn(v.y - __half2float(hy)));
    lo = *(uint32_t*)&lp;
}
// float2 -> packed fp16x2 (single)
__device__ __forceinline__ uint32_t pack2h(float2 v) {
    __half2 hp = __halves2half2(__float2half_rn(v.x), __float2half_rn(v.y));
    return *(uint32_t*)&hp;
}

#if TC_OK
// ---------------- tcgen05 helpers ----------------
__device__ __forceinline__ void tc_alloc(uint32_t smem_dst, uint32_t ncols) {
    asm volatile("tcgen05.alloc.cta_group::1.sync.aligned.shared::cta.b32 [%0], %1;"
                 :: "r"(smem_dst), "r"(ncols) : "memory");
}
__device__ __forceinline__ void tc_dealloc(uint32_t tmem, uint32_t ncols) {
    asm volatile("tcgen05.relinquish_alloc_permit.cta_group::1.sync.aligned;");
    asm volatile("tcgen05.dealloc.cta_group::1.sync.aligned.b32 %0, %1;" :: "r"(tmem), "r"(ncols));
}
__device__ __forceinline__ void tc_commit(uint32_t bar) {
    asm volatile("tcgen05.commit.cta_group::1.mbarrier::arrive::one.shared::cluster.b64 [%0];"
                 :: "r"(bar) : "memory");
}
__device__ __forceinline__ void tc_mma_f16_ss(uint32_t d, uint64_t ad, uint64_t bd,
                                              uint32_t idesc, uint32_t accum) {
    asm volatile("{\n\t.reg .pred p;\n\t"
                 "setp.ne.u32 p, %4, 0;\n\t"
                 "tcgen05.mma.cta_group::1.kind::f16 [%0], %1, %2, %3, {%5, %5, %5, %5}, p;\n\t}"
                 :: "r"(d), "l"(ad), "l"(bd), "r"(idesc), "r"(accum), "r"(0u) : "memory");
}
__device__ __forceinline__ void tc_fence_after() {
    asm volatile("tcgen05.fence::after_thread_sync;" ::: "memory");
}
#define LDTM_X32(r, addr) \
    asm volatile("tcgen05.ld.sync.aligned.32x32b.x32.b32 " \
        "{%0, %1, %2, %3, %4, %5, %6, %7, %8, %9, %10, %11, %12, %13, %14, %15, " \
        "%16, %17, %18, %19, %20, %21, %22, %23, %24, %25, %26, %27, %28, %29, %30, %31}, [%32];" \
        : "=r"((r)[0]), "=r"((r)[1]), "=r"((r)[2]), "=r"((r)[3]), \
          "=r"((r)[4]), "=r"((r)[5]), "=r"((r)[6]), "=r"((r)[7]), \
          "=r"((r)[8]), "=r"((r)[9]), "=r"((r)[10]), "=r"((r)[11]), \
          "=r"((r)[12]), "=r"((r)[13]), "=r"((r)[14]), "=r"((r)[15]), \
          "=r"((r)[16]), "=r"((r)[17]), "=r"((r)[18]), "=r"((r)[19]), \
          "=r"((r)[20]), "=r"((r)[21]), "=r"((r)[22]), "=r"((r)[23]), \
          "=r"((r)[24]), "=r"((r)[25]), "=r"((r)[26]), "=r"((r)[27]), \
          "=r"((r)[28]), "=r"((r)[29]), "=r"((r)[30]), "=r"((r)[31]) \
        : "r"(addr))
__device__ __forceinline__ void tc_wait_ld() {
    asm volatile("tcgen05.wait::ld.sync.aligned;" ::: "memory");
}
// SW64 K-major descriptor
static __device__ __forceinline__ uint64_t make_desc64(uint32_t addr) {
    const uint64_t base = (uint64_t(4) << 61) | (uint64_t(1) << 46) |
                          (uint64_t(32) << 32) | (uint64_t(1) << 16);
    return base | ((uint64_t)(addr >> 4) & 0x3FFFull);
}
#endif

// ---------------- weight transpose -> fp16 ----------------
__global__ void wsplit_kernel(const float* __restrict__ in,
                              __half* __restrict__ out,
                              int Kdim, int Ndim) {
    __shared__ float t[32][33];
    int n0 = blockIdx.x * 32, k0 = blockIdx.y * 32;
    int tx = threadIdx.x, ty = threadIdx.y;
    for (int r = ty; r < 32; r += 8)
        t[r][tx] = in[(size_t)(k0 + r) * Ndim + n0 + tx];
    __syncthreads();
    for (int r = ty; r < 32; r += 8)
        out[(size_t)(n0 + r) * Kdim + k0 + tx] = __float2half_rn(t[tx][r]);
}

// ---------------- fused: x -> fp16 single + pooling + attention rmsnorm ----------------
__global__ void pool_rmsnorm_kernel(const float* __restrict__ x,
                                    const float* __restrict__ w) {
    int row = blockIdx.x;
    int tid = threadIdx.x;
    const float* base = x + (size_t)row * POOLN * DIM;
    float local = 0.f;
    #pragma unroll
    for (int i = 0; i < DIM / 512; i++) {
        int d = (tid + i * 256) * 2;
        float2 s = make_float2(0.f, 0.f);
        #pragma unroll
        for (int p = 0; p < POOLN; p++) {
            float2 v = *(const float2*)&base[(size_t)p*DIM + d];
            size_t o = (size_t)(row * POOLN + p) * DIM + d;
            *(uint32_t*)&g_a_hi[o] = pack2h(v);
            s.x += v.x; s.y += v.y;
        }
        s.x *= (1.0f / POOLN); s.y *= (1.0f / POOLN);
        *(float2*)&g_queries[(size_t)row*DIM + d] = s;
        local += s.x * s.x + s.y * s.y;
    }
    __shared__ float red[256];
    red[tid] = local; __syncthreads();
    for (int st = 128; st > 0; st >>= 1) {
        if (tid < st) red[tid] += red[tid + st];
        __syncthreads();
    }
    float rstd = rsqrtf(red[0] / DIM + EPS);
    #pragma unroll
    for (int i = 0; i < DIM / 512; i++) {
        int d = (tid + i * 256) * 2;
        float2 qv = *(float2*)&g_queries[(size_t)row*DIM + d];
        float2 wv = *(const float2*)&w[d];
        float2 v = make_float2(qv.x * rstd * wv.x, qv.y * rstd * wv.y);
        *(uint32_t*)&g_qn_h[(size_t)row*DIM + d] = pack2h(v);
    }
}

// ---------------- fp16 GEMM: C[M,N] = A[M,K] @ B[N,K]^T ----------------
// a_single=1: A is single fp16 (skip Al).  half_out=1: fp16 output.
#define BM 256
#define BN 256
#define GK 4096
#define KITERS (GK/32)
#define A_TILE_B 8192u
#define B_TILE_B 16384u
#define STAGE_BYTES (4u*A_TILE_B + B_TILE_B)   // 49152
#define NSTAGE 4
#define GEMM_SMEM (NSTAGE*STAGE_BYTES + 1024)

__global__ __launch_bounds__(256, 1)
void gemm3_kernel(int N, int nbm, int nbn, int half_out, int a_single, int m_base,
                  const __grid_constant__ CUtensorMap mAh,
                  const __grid_constant__ CUtensorMap mAl,
                  const __grid_constant__ CUtensorMap mB,
                  const __half* __restrict__ Ah,
                  const __half* __restrict__ Al,
                  const __half* __restrict__ B,
                  float* __restrict__ C,
                  __half* __restrict__ Ch) {
    extern __shared__ char smraw[];
    char* smp = (char*)((((uintptr_t)smraw) + 1023) & ~(uintptr_t)1023);
    int tid = threadIdx.x;

    const int GM = 16;
    int bid = blockIdx.x;
    int group = bid / (GM * nbn);
    int first_m = group * GM;
    int gsz = min(nbm - first_m, GM);
    int pm = first_m + (bid % gsz);
    int pn = (bid % (GM * nbn)) / gsz;
    int m0 = m_base + pm * BM, n0 = pn * BN;

#if TC_OK
    uint32_t sb0 = s2u(smp);
    __shared__ __align__(8) unsigned long long full_b[NSTAGE], empty_b[NSTAGE], fin_b;
    __shared__ uint32_t tmem_ptr_sh;

    uint32_t full_a[NSTAGE], empty_a[NSTAGE], fin_a;
    #pragma unroll
    for (int i = 0; i < NSTAGE; i++) {
        full_a[i] = s2u(&full_b[i]);
        empty_a[i] = s2u(&empty_b[i]);
    }
    fin_a = s2u(&fin_b);

    if (tid < 32) tc_alloc(s2u(&tmem_ptr_sh), 512);
    if (tid == 0) {
        #pragma unroll
        for (int i = 0; i < NSTAGE; i++) {
            mbar_init(full_a[i], 1);
            mbar_init(empty_a[i], 1);
        }
        mbar_init(fin_a, 1);
    }
    __syncthreads();
    uint32_t tmem = tmem_ptr_sh;

    const uint32_t idesc = (1u<<4) | ((BN/8)<<17) | (8u<<24);
    uint32_t tx_bytes = a_single ? (2u*A_TILE_B + B_TILE_B) : STAGE_BYTES;

    if (tid == 32) {
        for (int it = 0; it < KITERS; it++) {
            int s = it % NSTAGE;
            uint32_t ph = ((it / NSTAGE) & 1) ^ 1u;
            mbar_wait(empty_a[s], ph);
            int k0 = it * 32;
            uint32_t sb = sb0 + s * STAGE_BYTES;
            uint32_t bar = full_a[s];
            mbar_expect_tx(bar, tx_bytes);
            tma_load_2d(sb,                &mAh, k0, m0,       bar);
            tma_load_2d(sb + 2u*A_TILE_B,  &mAh, k0, m0 + 128, bar);
            if (!a_single) {
                tma_load_2d(sb + A_TILE_B,     &mAl, k0, m0,       bar);
                tma_load_2d(sb + 3u*A_TILE_B,  &mAl, k0, m0 + 128, bar);
            }
            tma_load_2d(sb + 4u*A_TILE_B,  &mB,  k0, n0,       bar);
        }
    } else if (tid == 0) {
        for (int it = 0; it < KITERS; it++) {
            int s = it % NSTAGE;
            uint32_t ph = (it / NSTAGE) & 1;
            mbar_wait(full_a[s], ph);
            uint32_t sb = sb0 + s * STAGE_BYTES;
            uint64_t a0h = make_desc64(sb);
            uint64_t a0l = make_desc64(sb + A_TILE_B);
            uint64_t a1h = make_desc64(sb + 2u*A_TILE_B);
            uint64_t a1l = make_desc64(sb + 3u*A_TILE_B);
            uint64_t bd  = make_desc64(sb + 4u*A_TILE_B);
            #pragma unroll
            for (int ks = 0; ks < 2; ks++) {
                uint32_t acc = (it > 0 || ks > 0) ? 1u : 0u;
                uint64_t o = ks * 2;
                tc_mma_f16_ss(tmem,       a0h + o, bd + o, idesc, acc);
                tc_mma_f16_ss(tmem + 256, a1h + o, bd + o, idesc, acc);
                if (!a_single) {
                    tc_mma_f16_ss(tmem,       a0l + o, bd + o, idesc, 1u);
                    tc_mma_f16_ss(tmem + 256, a1l + o, bd + o, idesc, 1u);
                }
            }
            tc_commit(empty_a[s]);
        }
        tc_commit(fin_a);
    }

    __syncthreads();
    mbar_wait(fin_a, 0);
    tc_fence_after();

    float* stg = (float*)smp;
    int w = tid >> 5, lane = tid & 31;
    #pragma unroll
    for (int half = 0; half < 2; half++) {
        if (w < 4) {
            for (int ch = 0; ch < 8; ch++) {
                uint32_t r[32];
                LDTM_X32(r, tmem + half * 256 + ch * 32);
                tc_wait_ld();
                #pragma unroll
                for (int j = 0; j < 32; j++)
                    stg[(size_t)(w * 32 + lane) * 260 + ch * 32 + j] = __uint_as_float(r[j]);
            }
        }
        __syncthreads();
        int c4 = (tid & 63) * 4;
        if (half_out) {
            for (int rr = tid >> 6; rr < 128; rr += 4) {
                float4 v = *(float4*)&stg[(size_t)rr * 260 + c4];
                uint32_t p0 = pack2h(make_float2(v.x, v.y));
                uint32_t p1 = pack2h(make_float2(v.z, v.w));
                *(uint2*)&Ch[(size_t)(m0 + half * 128 + rr) * N + n0 + c4] =
                    make_uint2(p0, p1);
            }
        } else {
            for (int rr = tid >> 6; rr < 128; rr += 4) {
                float4 v = *(float4*)&stg[(size_t)rr * 260 + c4];
                *(float4*)&C[(size_t)(m0 + half * 128 + rr) * N + n0 + c4] = v;
            }
        }
        __syncthreads();
    }
    if (tid < 32) tc_dealloc(tmem, 512);
#else
    // mma.sync fallback (bare sm_103; not selected on GB300)
    __half* sAh = (__half*)smp;
    __half* sAl = sAh + 128 * 40;
    __half* sB  = sAl + 128 * 40;

    int lane = tid & 31, w = tid >> 5;
    int wm = w & 3, wn = w >> 2;

    for (int mh = 0; mh < 2; mh++)
    for (int nh = 0; nh < 2; nh++) {
        int m0h = m0 + mh * 128;
        int n0h = n0 + nh * 128;
        float acc[2][4][4];
        #pragma unroll
        for (int mi = 0; mi < 2; mi++)
            #pragma unroll
            for (int ni = 0; ni < 4; ni++)
                #pragma unroll
                for (int j = 0; j < 4; j++) acc[mi][ni][j] = 0.f;

        for (int k0 = 0; k0 < GK; k0 += 32) {
            __syncthreads();
            for (int cid = tid; cid < 512; cid += 256) {
                int r = cid >> 2, c = cid & 3;
                *(uint4*)&sAh[r*40 + c*8] = *(const uint4*)&Ah[(size_t)(m0h+r)*GK + k0 + c*8];
                if (!a_single)
                    *(uint4*)&sAl[r*40 + c*8] = *(const uint4*)&Al[(size_t)(m0h+r)*GK + k0 + c*8];
                *(uint4*)&sB [r*40 + c*8] = *(const uint4*)&B [(size_t)(n0h+r)*GK + k0 + c*8];
            }
            __syncthreads();
            #pragma unroll
            for (int ks = 0; ks < 2; ks++) {
                int kc = (lane & 3) * 2 + ks * 16;
                uint32_t ah[2][4], al[2][4];
                #pragma unroll
                for (int mi = 0; mi < 2; mi++) {
                    int r = wm * 32 + mi * 16 + (lane >> 2);
                    ah[mi][0] = *(uint32_t*)&sAh[r*40 + kc];
                    ah[mi][1] = *(uint32_t*)&sAh[(r+8)*40 + kc];
                    ah[mi][2] = *(uint32_t*)&sAh[r*40 + kc + 8];
                    ah[mi][3] = *(uint32_t*)&sAh[(r+8)*40 + kc + 8];
                    if (!a_single) {
                        al[mi][0] = *(uint32_t*)&sAl[r*40 + kc];
                        al[mi][1] = *(uint32_t*)&sAl[(r+8)*40 + kc];
                        al[mi][2] = *(uint32_t*)&sAl[r*40 + kc + 8];
                        al[mi][3] = *(uint32_t*)&sAl[(r+8)*40 + kc + 8];
                    }
                }
                #pragma unroll
                for (int ni = 0; ni < 4; ni++) {
                    int nr = wn * 64 + ni * 8 + (lane >> 2);
                    uint32_t b0 = *(uint32_t*)&sB[nr*40 + kc];
                    uint32_t b1 = *(uint32_t*)&sB[nr*40 + kc + 8];
                    #pragma unroll
                    for (int mi = 0; mi < 2; mi++) {
                        mma16816h(acc[mi][ni], ah[mi], b0, b1);
                        if (!a_single) mma16816h(acc[mi][ni], al[mi], b0, b1);
                    }
                }
            }
        }
        #pragma unroll
        for (int mi = 0; mi < 2; mi++)
            #pragma unroll
            for (int ni = 0; ni < 4; ni++) {
                int r = m0h + wm * 32 + mi * 16 + (lane >> 2);
                int c = n0h + wn * 64 + ni * 8 + (lane & 3) * 2;
                if (half_out) {
                    *(uint32_t*)&Ch[(size_t)r * N + c] =
                        pack2h(make_float2(acc[mi][ni][0], acc[mi][ni][1]));
                    *(uint32_t*)&Ch[(size_t)(r+8) * N + c] =
                        pack2h(make_float2(acc[mi][ni][2], acc[mi][ni][3]));
                } else {
                    *(float2*)&C[(size_t)r * N + c] = make_float2(acc[mi][ni][0], acc[mi][ni][1]);
                    *(float2*)&C[(size_t)(r+8) * N + c] = make_float2(acc[mi][ni][2], acc[mi][ni][3]);
                }
            }
    }
#endif
}

// ---------------- tensor-core attention: single-fp16 Q, 64-token chunks ----------------
#define SROW 514
#define QROW 132
#define VTROW 66
#define OFF_Q  65792
#define OFF_K  (OFF_Q + 8448)
#define OFF_RI (OFF_K + 16896)
#define ATT2_SMEM (OFF_RI + 128)

__global__ __launch_bounds__(256, 2)
void attention2_kernel(int seg_base) {
    extern __shared__ char asmem[];
    float* sS = (float*)asmem;
    __half* sQ = (__half*)(asmem + OFF_Q);
    __half* sK = (__half*)(asmem + OFF_K);
    float* rinv = (float*)(asmem + OFF_RI);

    int bid = blockIdx.x;
    int rt = bid & 1;
    int h  = (bid >> 1) & 31;
    int s  = seg_base + (bid >> 6);
    int q0 = s * RQ + rt * 32;
    int t0 = s * LSEG;

    int tid = threadIdx.x;
    int w = tid >> 5, lane = tid & 31;
    int wm = w & 1;
    int wn = w >> 1;
    int lr = lane >> 2, lc = lane & 3;

    // load Q (32 x 128 fp16, single) -> smem (pure copy)
    for (int i = tid; i < 32 * 32; i += 256) {
        int r = i >> 5, c4 = (i & 31) * 4;
        uint2 v = *(uint2*)&g_q_h[(size_t)(q0 + r) * DIM + h * HDIM + c4];
        *(uint2*)&sQ[r * QROW + c4] = v;
    }

    const float scale = rsqrtf((float)HDIM);

    // ---- phase 1: S = scale * Q K^T  (8 chunks of 64 tokens, 1 MMA per tile) ----
    for (int ck = 0; ck < 8; ck++) {
        __syncthreads();
        for (int i = tid; i < 64 * 32; i += 256) {
            int r = i >> 5, c4 = (i & 31) * 4;
            uint2 v = *(uint2*)&g_kv_h[(size_t)(t0 + ck * 64 + r) * KVW + h * HDIM + c4];
            *(uint2*)&sK[r * QROW + c4] = v;
        }
        __syncthreads();

        float acc[2][4];
        #pragma unroll
        for (int nt = 0; nt < 2; nt++)
            #pragma unroll
            for (int j = 0; j < 4; j++) acc[nt][j] = 0.f;
        int r0 = wm * 16 + lr;
        #pragma unroll
        for (int kk = 0; kk < 8; kk++) {
            int k0 = kk * 16;
            uint32_t ah[4];
            ah[0] = *(uint32_t*)&sQ[r0 * QROW + k0 + lc * 2];
            ah[1] = *(uint32_t*)&sQ[(r0 + 8) * QROW + k0 + lc * 2];
            ah[2] = *(uint32_t*)&sQ[r0 * QROW + k0 + 8 + lc * 2];
            ah[3] = *(uint32_t*)&sQ[(r0 + 8) * QROW + k0 + 8 + lc * 2];
            #pragma unroll
            for (int nt = 0; nt < 2; nt++) {
                int nb = wn * 16 + nt * 8;
                uint32_t b0 = *(uint32_t*)&sK[(nb + lr) * QROW + k0 + lc * 2];
                uint32_t b1 = *(uint32_t*)&sK[(nb + lr) * QROW + k0 + 8 + lc * 2];
                mma16816h(acc[nt], ah, b0, b1);
            }
        }
        #pragma unroll
        for (int nt = 0; nt < 2; nt++) {
            int col = ck * 64 + wn * 16 + nt * 8 + lc * 2;
            *(float2*)&sS[r0 * SROW + col] = make_float2(acc[nt][0] * scale, acc[nt][1] * scale);
            *(float2*)&sS[(r0 + 8) * SROW + col] = make_float2(acc[nt][2] * scale, acc[nt][3] * scale);
        }
    }
    __syncthreads();

    // ---- phase 2: softmax ----
    for (int j = 0; j < 4; j++) {
        int r = w * 4 + j;
        float m = -1e30f;
        for (int i = lane; i < LSEG; i += 32) m = fmaxf(m, sS[r * SROW + i]);
        #pragma unroll
        for (int o = 16; o; o >>= 1) m = fmaxf(m, __shfl_xor_sync(0xffffffffu, m, o));
        float sum = 0.f;
        for (int i = lane; i < LSEG; i += 32) {
            float e = __expf(sS[r * SROW + i] - m);
            sS[r * SROW + i] = e;
            sum += e;
        }
        #pragma unroll
        for (int o = 16; o; o >>= 1) sum += __shfl_xor_sync(0xffffffffu, sum, o);
        if (lane == 0) rinv[r] = 1.0f / sum;
    }

    // ---- phase 3: O = P V (P hi/lo, 2 MMAs; 8 chunks of 64 tokens) ----
    float oacc[4][4];
    #pragma unroll
    for (int nt = 0; nt < 4; nt++)
        #pragma unroll
        for (int j = 0; j < 4; j++) oacc[nt][j] = 0.f;

    for (int ck = 0; ck < 8; ck++) {
        __syncthreads();
        for (int i = tid; i < 64 * 64; i += 256) {
            int t = i >> 6, hd2 = (i & 63) * 2;
            uint32_t v = *(uint32_t*)&g_kv_h[(size_t)(t0 + ck * 64 + t) * KVW
                                             + NH * HDIM + h * HDIM + hd2];
            __half2 hv = *(__half2*)&v;
            sK[hd2 * VTROW + t] = __low2half(hv);
            sK[(hd2 + 1) * VTROW + t] = __high2half(hv);
        }
        __syncthreads();

        #pragma unroll
        for (int kk = 0; kk < 4; kk++) {
            int kt = ck * 64 + kk * 16;
            int kl = kk * 16;
            int r0 = wm * 16 + lr;
            float2 p0 = *(float2*)&sS[r0 * SROW + kt + lc * 2];
            float2 p1 = *(float2*)&sS[(r0 + 8) * SROW + kt + lc * 2];
            float2 p2 = *(float2*)&sS[r0 * SROW + kt + 8 + lc * 2];
            float2 p3 = *(float2*)&sS[(r0 + 8) * SROW + kt + 8 + lc * 2];
            uint32_t ah[4], al[4];
            split2h(p0, ah[0], al[0]);
            split2h(p1, ah[1], al[1]);
            split2h(p2, ah[2], al[2]);
            split2h(p3, ah[3], al[3]);
            #pragma unroll
            for (int nt = 0; nt < 4; nt++) {
                int hd0 = wn * 32 + nt * 8;
                uint32_t b0 = *(uint32_t*)&sK[(hd0 + lr) * VTROW + kl + lc * 2];
                uint32_t b1 = *(uint32_t*)&sK[(hd0 + lr) * VTROW + kl + 8 + lc * 2];
                mma16816h(oacc[nt], ah, b0, b1);
                mma16816h(oacc[nt], al, b0, b1);
            }
        }
    }

    // ---- writeback: normalize, emit single fp16 ----
    {
        int r0 = wm * 16 + lr;
        float ri0 = rinv[r0], ri1 = rinv[r0 + 8];
        #pragma unroll
        for (int nt = 0; nt < 4; nt++) {
            int c0 = h * HDIM + wn * 32 + nt * 8 + lc * 2;
            *(uint32_t*)&g_o_h[(size_t)(q0 + r0) * DIM + c0] =
                pack2h(make_float2(oacc[nt][0] * ri0, oacc[nt][1] * ri0));
            *(uint32_t*)&g_o_h[(size_t)(q0 + r0 + 8) * DIM + c0] =
                pack2h(make_float2(oacc[nt][2] * ri1, oacc[nt][3] * ri1));
        }
    }
}

// ---------------- final: residual + rmsnorm ----------------
__global__ void final_kernel(const float* __restrict__ w, float* __restrict__ out) {
    int row = blockIdx.x;
    int tid = threadIdx.x;
    float vals[DIM / 256];
    float local = 0.f;
    #pragma unroll
    for (int i = 0; i < DIM / 256; i++) {
        int d = tid + i * 256;
        float v = g_tmp[(size_t)row * DIM + d] + g_queries[(size_t)row * DIM + d];
        vals[i] = v;
        local += v * v;
    }
    __shared__ float red[256];
    red[tid] = local; __syncthreads();
    for (int st = 128; st > 0; st >>= 1) {
        if (tid < st) red[tid] += red[tid + st];
        __syncthreads();
    }
    float rstd = rsqrtf(red[0] / DIM + EPS);
    #pragma unroll
    for (int i = 0; i < DIM / 256; i++) {
        int d = tid + i * 256;
        out[(size_t)row * DIM + d] = vals[i] * rstd * w[d];
    }
}

// ---------------- host: tensormap encode ----------------
typedef CUresult (*PFN_tmEncode)(CUtensorMap*, CUtensorMapDataType, cuuint32_t, void*,
                                 const cuuint64_t*, const cuuint64_t*, const cuuint32_t*,
                                 const cuuint32_t*, CUtensorMapInterleave, CUtensorMapSwizzle,
                                 CUtensorMapL2promotion, CUtensorMapFloatOOBfill);

static PFN_tmEncode get_encoder() {
    void* p = nullptr;
#if CUDART_VERSION >= 12050
    cudaDriverEntryPointQueryResult qr;
    cudaGetDriverEntryPointByVersion("cuTensorMapEncodeTiled", &p, 12000,
                                     cudaEnableDefault, &qr);
#else
    cudaGetDriverEntryPoint("cuTensorMapEncodeTiled", &p, cudaEnableDefault);
#endif
    return (PFN_tmEncode)p;
}

static void enc2d(PFN_tmEncode enc, CUtensorMap* m, void* base,
                  uint64_t rows, uint32_t boxRows) {
    cuuint64_t dims[2]    = {GK, rows};
    cuuint64_t strides[1] = {GK * 2};
    cuuint32_t box[2]     = {32, boxRows};
    cuuint32_t es[2]      = {1, 1};
    enc(m, CU_TENSOR_MAP_DATA_TYPE_FLOAT16, 2, base, dims, strides, box, es,
        CU_TENSOR_MAP_INTERLEAVE_NONE, CU_TENSOR_MAP_SWIZZLE_64B,
        CU_TENSOR_MAP_L2_PROMOTION_L2_128B, CU_TENSOR_MAP_FLOAT_OOB_FILL_NONE);
}

// ---------------- launch ----------------
extern "C" void kernel_launch(void* const* d_in, const int* in_sizes, int n_in,
                              void* d_out, int out_size) {
    const float* x      = (const float*)d_in[0];
    const float* attn_w = (const float*)d_in[1];
    const float* wq     = (const float*)d_in[2];
    const float* wkv    = (const float*)d_in[3];
    const float* wo     = (const float*)d_in[4];
    const float* out_w  = (const float*)d_in[5];
    float* out = (float*)d_out;

    float *ptmp;
    __half *pqh, *pkvh, *pah, *pbkv, *pbq, *pbo, *pqnh, *poh;
    cudaGetSymbolAddress((void**)&pqh,  g_q_h);
    cudaGetSymbolAddress((void**)&pkvh, g_kv_h);
    cudaGetSymbolAddress((void**)&ptmp, g_tmp);
    cudaGetSymbolAddress((void**)&pah,  g_a_hi);
    cudaGetSymbolAddress((void**)&pbkv, g_bkv);
    cudaGetSymbolAddress((void**)&pbq,  g_bq);
    cudaGetSymbolAddress((void**)&pbo,  g_bo);
    cudaGetSymbolAddress((void**)&pqnh, g_qn_h);
    cudaGetSymbolAddress((void**)&poh,  g_o_h);

    PFN_tmEncode enc = get_encoder();
    CUtensorMap mQA, mQB;
    CUtensorMap mKA, mKB;
    CUtensorMap mOA, mOB;
    enc2d(enc, &mQA, pqnh, NQ,   128);
    enc2d(enc, &mQB, pbq,  DIM,  256);
    enc2d(enc, &mKA, pah,  NTOK, 128);
    enc2d(enc, &mKB, pbkv, KVW,  256);
    enc2d(enc, &mOA, poh,  NQ,   128);
    enc2d(enc, &mOB, pbo,  DIM,  256);

    cudaFuncSetAttribute(attention2_kernel,
                         cudaFuncAttributeMaxDynamicSharedMemorySize, (int)ATT2_SMEM);
    cudaFuncSetAttribute(gemm3_kernel,
                         cudaFuncAttributeMaxDynamicSharedMemorySize, (int)GEMM_SMEM);

    // side stream + events (created once; host objects only)
    static cudaStream_t s1 = nullptr;
    static cudaEvent_t evR = nullptr, evW = nullptr, evPool = nullptr;
    static cudaEvent_t evKV0 = nullptr, evKV1 = nullptr;
    if (s1 == nullptr) {
        cudaStreamCreateWithFlags(&s1, cudaStreamNonBlocking);
        cudaEventCreateWithFlags(&evR,    cudaEventDisableTiming);
        cudaEventCreateWithFlags(&evW,    cudaEventDisableTiming);
        cudaEventCreateWithFlags(&evPool, cudaEventDisableTiming);
        cudaEventCreateWithFlags(&evKV0,  cudaEventDisableTiming);
        cudaEventCreateWithFlags(&evKV1,  cudaEventDisableTiming);
    }

    // fork: weight transposes on s1, pooling on main
    cudaEventRecord(evR, 0);
    cudaStreamWaitEvent(s1, evR, 0);
    wsplit_kernel<<<dim3(KVW/32, DIM/32), dim3(32,8), 0, s1>>>(wkv, pbkv, DIM, KVW);
    wsplit_kernel<<<dim3(DIM/32, DIM/32), dim3(32,8), 0, s1>>>(wq, pbq, DIM, DIM);
    wsplit_kernel<<<dim3(DIM/32, DIM/32), dim3(32,8), 0, s1>>>(wo, pbo, DIM, DIM);
    cudaEventRecord(evW, s1);

    pool_rmsnorm_kernel<<<NQ, 256>>>(x, attn_w);
    cudaEventRecord(evPool, 0);

    // kv = x @ wkv on s1, two M-halves (fp16 output, single-fp16 A)
    cudaStreamWaitEvent(s1, evPool, 0);
    gemm3_kernel<<<(NTOK/2/BM)*(KVW/BN), 256, GEMM_SMEM, s1>>>(KVW, NTOK/2/BM, KVW/BN, 1, 1, 0,
        mKA, mKA, mKB, pah, pah, pbkv, nullptr, pkvh);
    cudaEventRecord(evKV0, s1);
    gemm3_kernel<<<(NTOK/2/BM)*(KVW/BN), 256, GEMM_SMEM, s1>>>(KVW, NTOK/2/BM, KVW/BN, 1, 1, NTOK/2,
        mKA, mKA, mKB, pah, pah, pbkv, nullptr, pkvh);
    cudaEventRecord(evKV1, s1);

    // q = qn @ wq on main (fp16 output, single-fp16 A)
    cudaStreamWaitEvent(0, evW, 0);
    gemm3_kernel<<<(NQ/BM)*(DIM/BN), 256, GEMM_SMEM>>>(DIM, NQ/BM, DIM/BN, 1, 1, 0,
        mQA, mQA, mQB, pqnh, pqnh, pbq, nullptr, pqh);

    // attention half 0 (segments 0-15) overlaps kv half 1
    cudaStreamWaitEvent(0, evKV0, 0);
    attention2_kernel<<<SEGN * NH, 256, ATT2_SMEM>>>(0);
    // attention half 1 (segments 16-31)
    cudaStreamWaitEvent(0, evKV1, 0);
    attention2_kernel<<<SEGN * NH, 256, ATT2_SMEM>>>(SEGN / 2);

    // tmp = o @ wo (fp32 output, single-fp16 A)
    gemm3_kernel<<<(NQ/BM)*(DIM/BN), 256, GEMM_SMEM>>>(DIM, NQ/BM, DIM/BN, 0, 1, 0,
        mOA, mOA, mOB, poh, poh, pbo, ptmp, nullptr);
    // residual + rmsnorm
    final_kernel<<<NQ, 256>>>(out_w, out);
}